// round 12
// baseline (speedup 1.0000x reference)
#include <cuda_runtime.h>
#include <cuda_fp16.h>
#include <cstdint>
#include <math.h>

// ---------------- problem constants ----------------
#define BATCH   8
#define NNODE   2048
#define MTOT    16384
#define HID     256
#define ATN     64
#define EMB     255
#define QKV     384
#define KDIM    256
#define CAP     64
#define CPAD    76
#define HPAD    72

// ---------------- device scratch ----------------
__device__ __align__(16) __half g_feats[MTOT*HID];
__device__ __align__(16) __half g_h0[MTOT*HID];
__device__ __align__(16) __half g_h1[MTOT*HID];
__device__ __align__(16) __half g_q[MTOT*ATN];
__device__ __align__(16) __half g_kh[MTOT*ATN];
__device__ __align__(16) __half g_vh[(size_t)MTOT*HID];
__device__ __align__(16) __half g_WhT[HID*KDIM];
__device__ __align__(16) __half g_WqkvT[QKV*KDIM];
__device__ int   g_nbr[(size_t)MTOT*CAP];
__device__ int   g_cnt[MTOT];

// ---------------- stream/event for fork-join (created before harness baseline)
static cudaStream_t g_s2 = nullptr;
static cudaEvent_t  g_evFork = nullptr, g_evJoin = nullptr;
struct _StreamInit {
    _StreamInit() {
        cudaStreamCreateWithFlags(&g_s2, cudaStreamNonBlocking);
        cudaEventCreateWithFlags(&g_evFork, cudaEventDisableTiming);
        cudaEventCreateWithFlags(&g_evJoin, cudaEventDisableTiming);
    }
};
static _StreamInit _streamInit;

__device__ __forceinline__ uint32_t smem_u32(const void* p) {
    uint32_t a;
    asm("{ .reg .u64 t; cvta.to.shared.u64 t, %1; cvt.u32.u64 %0, t; }" : "=r"(a) : "l"(p));
    return a;
}
__device__ __forceinline__ void cp16(uint32_t dst, const void* src) {
    asm volatile("cp.async.cg.shared.global [%0], [%1], 16;" :: "r"(dst), "l"(src) : "memory");
}
__device__ __forceinline__ void ldm_x4(uint32_t* r, uint32_t addr) {
    asm volatile("ldmatrix.sync.aligned.m8n8.x4.shared.b16 {%0,%1,%2,%3}, [%4];"
        : "=r"(r[0]), "=r"(r[1]), "=r"(r[2]), "=r"(r[3]) : "r"(addr));
}
__device__ __forceinline__ void mma_f16(float* c, const uint32_t* a, const uint32_t* b) {
    asm volatile(
        "mma.sync.aligned.m16n8k16.row.col.f32.f16.f16.f32 "
        "{%0,%1,%2,%3}, {%4,%5,%6,%7}, {%8,%9}, {%0,%1,%2,%3};"
        : "+f"(c[0]), "+f"(c[1]), "+f"(c[2]), "+f"(c[3])
        : "r"(a[0]), "r"(a[1]), "r"(a[2]), "r"(a[3]), "r"(b[0]), "r"(b[1]));
}

// ---------------- adjacency scan (standalone, low-reg, runs on s2) ----------
__global__ void __launch_bounds__(256)
scan_kernel(const float* __restrict__ adj) {
    int row  = blockIdx.x * 8 + (threadIdx.x >> 5);
    int lane = threadIdx.x & 31;
    const float4* ar = reinterpret_cast<const float4*>(adj + (size_t)row * NNODE);
    int* dst = g_nbr + (size_t)row * CAP;
    int base = 0;
    for (int j0 = 0; j0 < NNODE; j0 += 128) {
        float4 v = ar[(j0 >> 2) + lane];
        int h0 = v.x > 0.f, h1 = v.y > 0.f, h2 = v.z > 0.f, h3 = v.w > 0.f;
        int c4 = h0 + h1 + h2 + h3;
        int sc = c4;
        #pragma unroll
        for (int o = 1; o < 32; o <<= 1) {
            int nx = __shfl_up_sync(0xffffffffu, sc, o);
            if (lane >= o) sc += nx;
        }
        int pos = base + sc - c4;
        int jb = j0 + lane*4;
        if (h0) { if (pos < CAP) dst[pos] = jb;   pos++; }
        if (h1) { if (pos < CAP) dst[pos] = jb+1; pos++; }
        if (h2) { if (pos < CAP) dst[pos] = jb+2; pos++; }
        if (h3) { if (pos < CAP) dst[pos] = jb+3; pos++; }
        base += __shfl_sync(0xffffffffu, sc, 31);
    }
    if (lane == 0) g_cnt[row] = min(base, CAP);
}

// ---------------- prep: feats + weight transpose ----------
#define NB_FEATS 8192
#define NB_W     384

__global__ void __launch_bounds__(256)
prep_kernel(const int* __restrict__ x, const int* __restrict__ cue,
            const float* __restrict__ emb,
            const float* __restrict__ Wh, const float* __restrict__ Wq,
            const float* __restrict__ Wk, const float* __restrict__ Wv) {
    int bid = blockIdx.x;
    int t = threadIdx.x;
    if (bid < NB_FEATS) {
        int m = bid * 2 + (t >> 7);
        int d0 = (t & 127) * 2;
        int xi = x[m];
        float cuev = (float)cue[m];
        const float* er = emb + (size_t)xi * EMB;
        float v0 = (d0     < EMB) ? er[d0]   : cuev;
        float v1 = (d0 + 1 < EMB) ? er[d0+1] : cuev;
        *reinterpret_cast<__half2*>(&g_feats[(size_t)m*HID + d0]) = __floats2half2_rn(v0, v1);
    } else {
        int idx = (bid - NB_FEATS) * 256 + t;
        int n = idx >> 8, k = idx & 255;
        if (idx < 256*256)
            g_WhT[n*256 + k] = __float2half(Wh[k*256 + n]);
        float v = (n < 64) ? Wq[k*64 + n] : (n < 128) ? Wk[k*64 + (n-64)] : Wv[k*256 + (n-128)];
        g_WqkvT[n*256 + k] = __float2half(v);
    }
}

// ---------------- fp16 GEMM, ldmatrix + cp.async 2-stage, tile 128x128xBK64 --
#define TILE_HALVES (128*HPAD)
#define STAGE_HALVES (2*TILE_HALVES)
#define SMEM_BYTES  (2*STAGE_HALVES*2)

template<int MODE>
__global__ void __launch_bounds__(256, 2)
gemm_h_kernel(const __half* __restrict__ A, const __half* __restrict__ BT,
              __half* __restrict__ C, const float* __restrict__ bias,
              __half* __restrict__ qo, __half* __restrict__ kho, __half* __restrict__ vho) {
    extern __shared__ __half sm[];
    const int tid = threadIdx.x;
    const int lane = tid & 31, wid = tid >> 5;
    const int wm = (wid & 3) * 32;
    const int wn = (wid >> 2) * 64;
    const int m0 = blockIdx.y * 128;
    const int n0 = blockIdx.x * 128;
    const int r = lane >> 2, cql = lane & 3;
    const uint32_t sbase = smem_u32(sm);

    const uint32_t aBase = (uint32_t)((wm + (lane & 15)) * HPAD + ((lane >> 4) << 3));
    const uint32_t bBase = (uint32_t)((wn + (lane & 7) + ((lane >> 4) << 3)) * HPAD
                                      + (((lane >> 3) & 1) << 3));

    float acc[2][8][4];
    #pragma unroll
    for (int i = 0; i < 2; i++)
        #pragma unroll
        for (int j = 0; j < 8; j++)
            #pragma unroll
            for (int e = 0; e < 4; e++) acc[i][j][e] = 0.0f;

    auto stage = [&](int buf, int kt) {
        uint32_t dbase = sbase + (uint32_t)(buf * STAGE_HALVES) * 2u;
        #pragma unroll
        for (int i = 0; i < 4; i++) {
            int idx = tid + i*256;
            int row = idx >> 3, ck = (idx & 7) << 3;
            cp16(dbase + (uint32_t)(row*HPAD + ck)*2u,
                 A + (size_t)(m0+row)*KDIM + kt + ck);
        }
        #pragma unroll
        for (int i = 0; i < 4; i++) {
            int idx = tid + i*256;
            int row = idx >> 3, ck = (idx & 7) << 3;
            cp16(dbase + (uint32_t)(TILE_HALVES + row*HPAD + ck)*2u,
                 BT + (size_t)(n0+row)*KDIM + kt + ck);
        }
        asm volatile("cp.async.commit_group;" ::: "memory");
    };

    stage(0, 0);
    for (int c = 0; c < 4; c++) {
        asm volatile("cp.async.wait_group 0;" ::: "memory");
        __syncthreads();
        if (c < 3) stage((c+1) & 1, (c+1)*64);

        const uint32_t As = sbase + (uint32_t)((c & 1) * STAGE_HALVES) * 2u;
        const uint32_t Bs = As + (uint32_t)TILE_HALVES * 2u;

        #pragma unroll
        for (int k16 = 0; k16 < 4; k16++) {
            const uint32_t kk = k16 * 16;
            uint32_t a[2][4], b[8][2];
            #pragma unroll
            for (int i = 0; i < 2; i++)
                ldm_x4(a[i], As + (aBase + (uint32_t)(i*16*HPAD) + kk) * 2u);
            #pragma unroll
            for (int p = 0; p < 4; p++) {
                uint32_t rb[4];
                ldm_x4(rb, Bs + (bBase + (uint32_t)(p*16*HPAD) + kk) * 2u);
                b[2*p][0]   = rb[0]; b[2*p][1]   = rb[1];
                b[2*p+1][0] = rb[2]; b[2*p+1][1] = rb[3];
            }
            #pragma unroll
            for (int i = 0; i < 2; i++)
                #pragma unroll
                for (int j = 0; j < 8; j++)
                    mma_f16(acc[i][j], a[i], b[j]);
        }
        __syncthreads();
    }

    #pragma unroll
    for (int i = 0; i < 2; i++) {
        int row = m0 + wm + i*16 + r;
        #pragma unroll
        for (int j = 0; j < 8; j++) {
            int col = n0 + wn + j*8 + cql*2;
            float v0 = acc[i][j][0], v1 = acc[i][j][1];
            float v2 = acc[i][j][2], v3 = acc[i][j][3];
            if (MODE == 0) {
                float b0 = bias[col], b1 = bias[col+1];
                v0 = fmaxf(v0 + b0, 0.f); v1 = fmaxf(v1 + b1, 0.f);
                v2 = fmaxf(v2 + b0, 0.f); v3 = fmaxf(v3 + b1, 0.f);
                *reinterpret_cast<__half2*>(&C[(size_t)row*HID + col])     = __floats2half2_rn(v0, v1);
                *reinterpret_cast<__half2*>(&C[(size_t)(row+8)*HID + col]) = __floats2half2_rn(v2, v3);
            } else {
                if (col < 64) {
                    *reinterpret_cast<__half2*>(&qo[(size_t)row*ATN + col])     = __floats2half2_rn(v0, v1);
                    *reinterpret_cast<__half2*>(&qo[(size_t)(row+8)*ATN + col]) = __floats2half2_rn(v2, v3);
                } else if (col < 128) {
                    *reinterpret_cast<__half2*>(&kho[(size_t)row*ATN + col - 64])     = __floats2half2_rn(v0, v1);
                    *reinterpret_cast<__half2*>(&kho[(size_t)(row+8)*ATN + col - 64]) = __floats2half2_rn(v2, v3);
                } else {
                    *reinterpret_cast<__half2*>(&vho[(size_t)row*HID + col - 128])     = __floats2half2_rn(v0, v1);
                    *reinterpret_cast<__half2*>(&vho[(size_t)(row+8)*HID + col - 128]) = __floats2half2_rn(v2, v3);
                }
            }
        }
    }
}

// ---------------- sparse graph attention: warp/node, batched cp.async ring --
template<int LAST>
__global__ void __launch_bounds__(256, 5)
attn_kernel(const __half* __restrict__ q, const __half* __restrict__ kh,
            const __half* __restrict__ vh, __half* __restrict__ hout,
            const float* __restrict__ gcb,
            const float* __restrict__ Wc, const float* __restrict__ bc,
            float* __restrict__ out) {
    const int wid = threadIdx.x >> 5, lane = threadIdx.x & 31;
    const int node = blockIdx.x * 8 + wid;
    __shared__ float qs[8][64];
    __shared__ float ps[8][CPAD];
    __shared__ int   js[8][CPAD];
    __shared__ __align__(16) uint4 vring[8][8][32];

    const int cnt = g_cnt[node];
    float outv[8];

    if (cnt > 0) {
        float2 qv = __half22float2(reinterpret_cast<const __half2*>(q + (size_t)node*ATN)[lane]);
        qs[wid][2*lane]   = qv.x;
        qs[wid][2*lane+1] = qv.y;
        __syncwarp();

        const int* nl = g_nbr + (size_t)node * CAP;
        for (int t0 = 0; t0 < cnt; t0 += 32) {
            int jn = t0 + lane;
            if (jn < cnt) {
                int j = nl[jn];
                js[wid][jn] = j;
                const uint4* kp = reinterpret_cast<const uint4*>(kh + (size_t)j*ATN);
                float d = 0.0f;
                #pragma unroll
                for (int b = 0; b < 8; b++) {
                    uint4 kk = kp[b];
                    const __half2* hp = reinterpret_cast<const __half2*>(&kk);
                    #pragma unroll
                    for (int e = 0; e < 4; e++) {
                        float2 f = __half22float2(hp[e]);
                        d = fmaf(qs[wid][b*8 + 2*e],     f.x, d);
                        d = fmaf(qs[wid][b*8 + 2*e + 1], f.y, d);
                    }
                }
                ps[wid][jn] = d;
            }
        }
        __syncwarp();

        float mx = -1e30f;
        for (int jn = lane; jn < cnt; jn += 32) mx = fmaxf(mx, ps[wid][jn]);
        #pragma unroll
        for (int o = 16; o; o >>= 1) mx = fmaxf(mx, __shfl_xor_sync(0xffffffffu, mx, o));
        float sum = 0.0f;
        for (int jn = lane; jn < cnt; jn += 32) {
            float e = __expf(ps[wid][jn] - mx);
            ps[wid][jn] = e;
            sum += e;
        }
        #pragma unroll
        for (int o = 16; o; o >>= 1) sum += __shfl_xor_sync(0xffffffffu, sum, o);
        float sinv = 1.0f / sum;
        __syncwarp();

        const uint32_t ringb = smem_u32(&vring[wid][0][0]) + (uint32_t)lane * 16u;
        const int cm1 = cnt - 1;
        #pragma unroll
        for (int r = 0; r < 4; r++) {
            int idx = (r < cnt) ? r : cm1;
            cp16(ringb + (uint32_t)r * 512u, vh + (size_t)js[wid][idx]*HID + lane*8);
        }
        asm volatile("cp.async.commit_group;" ::: "memory");
        #pragma unroll
        for (int r = 4; r < 8; r++) {
            int idx = (r < cnt) ? r : cm1;
            cp16(ringb + (uint32_t)r * 512u, vh + (size_t)js[wid][idx]*HID + lane*8);
        }
        asm volatile("cp.async.commit_group;" ::: "memory");

        float acc[8] = {0,0,0,0,0,0,0,0};
        const int ng = (cnt + 3) >> 2;
        for (int g = 0; g < ng; g++) {
            asm volatile("cp.async.wait_group 1;" ::: "memory");
            const int base = g * 4;
            #pragma unroll
            for (int r = 0; r < 4; r++) {
                int row = base + r;
                float p = (row < cnt) ? ps[wid][row] : 0.0f;
                uint4 vv = vring[wid][row & 7][lane];
                const __half2* hp = reinterpret_cast<const __half2*>(&vv);
                #pragma unroll
                for (int e = 0; e < 4; e++) {
                    float2 f = __half22float2(hp[e]);
                    acc[2*e]   = fmaf(p, f.x, acc[2*e]);
                    acc[2*e+1] = fmaf(p, f.y, acc[2*e+1]);
                }
            }
            #pragma unroll
            for (int r = 0; r < 4; r++) {
                int row = base + 8 + r;
                int idx = (row < cnt) ? row : cm1;
                cp16(ringb + (uint32_t)(row & 7) * 512u, vh + (size_t)js[wid][idx]*HID + lane*8);
            }
            asm volatile("cp.async.commit_group;" ::: "memory");
        }

        #pragma unroll
        for (int e = 0; e < 8; e++) {
            float val = acc[e] * sinv + gcb[lane*8 + e];
            outv[e] = 1.0f / (1.0f + __expf(-val));
        }
    } else {
        #pragma unroll
        for (int e = 0; e < 8; e++)
            outv[e] = 1.0f / (1.0f + __expf(-gcb[lane*8 + e]));
    }

    if (LAST) {
        float a0 = 0.0f, a1 = 0.0f;
        #pragma unroll
        for (int e = 0; e < 8; e++) {
            int c = lane*8 + e;
            a0 = fmaf(outv[e], Wc[2*c],     a0);
            a1 = fmaf(outv[e], Wc[2*c + 1], a1);
        }
        #pragma unroll
        for (int o = 16; o; o >>= 1) {
            a0 += __shfl_xor_sync(0xffffffffu, a0, o);
            a1 += __shfl_xor_sync(0xffffffffu, a1, o);
        }
        if (lane == 0) {
            a0 += bc[0]; a1 += bc[1];
            float m = fmaxf(a0, a1);
            float e0 = __expf(a0 - m), e1 = __expf(a1 - m);
            float inv = 1.0f / (e0 + e1);
            out[node*2 + 0] = e0 * inv;
            out[node*2 + 1] = e1 * inv;
        }
    } else {
        __half2 ov[4];
        #pragma unroll
        for (int e = 0; e < 4; e++)
            ov[e] = __floats2half2_rn(outv[2*e], outv[2*e+1]);
        *reinterpret_cast<uint4*>(hout + (size_t)node*HID + lane*8) = *reinterpret_cast<uint4*>(ov);
    }
}

// ---------------- launch ----------------
extern "C" void kernel_launch(void* const* d_in, const int* in_sizes, int n_in,
                              void* d_out, int out_size) {
    const int*   x   = (const int*)  d_in[0];
    const int*   cue = (const int*)  d_in[1];
    const float* adj = (const float*)d_in[2];
    const float* emb = (const float*)d_in[3];
    const float* Wh  = (const float*)d_in[4];
    const float* bh  = (const float*)d_in[5];
    const float* Wq  = (const float*)d_in[6];
    const float* Wk  = (const float*)d_in[7];
    const float* Wv  = (const float*)d_in[8];
    const float* gcb = (const float*)d_in[9];
    const float* Wc  = (const float*)d_in[10];
    const float* bc  = (const float*)d_in[11];
    float* out = (float*)d_out;

    void *p_feats, *p_h0, *p_h1, *p_q, *p_kh, *p_vh, *p_WhT, *p_WqkvT;
    cudaGetSymbolAddress(&p_feats, g_feats);
    cudaGetSymbolAddress(&p_h0,    g_h0);
    cudaGetSymbolAddress(&p_h1,    g_h1);
    cudaGetSymbolAddress(&p_q,     g_q);
    cudaGetSymbolAddress(&p_kh,    g_kh);
    cudaGetSymbolAddress(&p_vh,    g_vh);
    cudaGetSymbolAddress(&p_WhT,   g_WhT);
    cudaGetSymbolAddress(&p_WqkvT, g_WqkvT);
    __half* feats = (__half*)p_feats;
    __half* h0    = (__half*)p_h0;
    __half* h1    = (__half*)p_h1;
    __half* qbuf  = (__half*)p_q;
    __half* khb   = (__half*)p_kh;
    __half* vhb   = (__half*)p_vh;
    __half* WhT   = (__half*)p_WhT;
    __half* WqkvT = (__half*)p_WqkvT;

    cudaFuncSetAttribute(gemm_h_kernel<0>, cudaFuncAttributeMaxDynamicSharedMemorySize, SMEM_BYTES);
    cudaFuncSetAttribute(gemm_h_kernel<1>, cudaFuncAttributeMaxDynamicSharedMemorySize, SMEM_BYTES);

    // ---- fork: adjacency scan on s2, concurrent with prep + gemm0 + qkv0 ----
    cudaEventRecord(g_evFork, 0);
    cudaStreamWaitEvent(g_s2, g_evFork, 0);
    scan_kernel<<<NNODE, 256, 0, g_s2>>>(adj);
    cudaEventRecord(g_evJoin, g_s2);

    // main stream: feats + weights, then GEMM chain
    prep_kernel<<<NB_FEATS + NB_W, 256>>>(x, cue, emb, Wh, Wq, Wk, Wv);
    gemm_h_kernel<0><<<dim3(2, 128), 256, SMEM_BYTES>>>(feats, WhT, h0, bh, nullptr, nullptr, nullptr);
    gemm_h_kernel<1><<<dim3(3, 128), 256, SMEM_BYTES>>>(h0, WqkvT, nullptr, nullptr, qbuf, khb, vhb);

    // join: attn0 needs neighbor lists
    cudaStreamWaitEvent(0, g_evJoin, 0);
    attn_kernel<0><<<MTOT/8, 256>>>(qbuf, khb, vhb, h1, gcb, nullptr, nullptr, nullptr);

    // layer 1 + fused classifier
    gemm_h_kernel<1><<<dim3(3, 128), 256, SMEM_BYTES>>>(h1, WqkvT, nullptr, nullptr, qbuf, khb, vhb);
    attn_kernel<1><<<MTOT/8, 256>>>(qbuf, khb, vhb, nullptr, gcb, Wc, bc, out);
}

// round 13
// speedup vs baseline: 1.0054x; 1.0054x over previous
#include <cuda_runtime.h>
#include <cuda_fp16.h>
#include <cstdint>
#include <math.h>

// ---------------- problem constants ----------------
#define BATCH   8
#define NNODE   2048
#define MTOT    16384
#define HID     256
#define ATN     64
#define EMB     255
#define QKV     384
#define KDIM    256
#define CAP     64
#define CPAD    76
#define HPAD    72

// ---------------- device scratch ----------------
__device__ __align__(16) __half g_feats[MTOT*HID];
__device__ __align__(16) __half g_h0[MTOT*HID];
__device__ __align__(16) __half g_h1[MTOT*HID];
__device__ __align__(16) __half g_q[MTOT*ATN];
__device__ __align__(16) __half g_kh[MTOT*ATN];
__device__ __align__(16) __half g_vh[(size_t)MTOT*HID];
__device__ __align__(16) __half g_WhT[HID*KDIM];
__device__ __align__(16) __half g_WqkvT[QKV*KDIM];
__device__ int   g_nbr[(size_t)MTOT*CAP];
__device__ int   g_cnt[MTOT];

// ---------------- stream/event for fork-join ----------------
static cudaStream_t g_s2 = nullptr;
static cudaEvent_t  g_evFork = nullptr, g_evJoin = nullptr;
struct _StreamInit {
    _StreamInit() {
        cudaStreamCreateWithFlags(&g_s2, cudaStreamNonBlocking);
        cudaEventCreateWithFlags(&g_evFork, cudaEventDisableTiming);
        cudaEventCreateWithFlags(&g_evJoin, cudaEventDisableTiming);
    }
};
static _StreamInit _streamInit;

__device__ __forceinline__ uint32_t smem_u32(const void* p) {
    uint32_t a;
    asm("{ .reg .u64 t; cvta.to.shared.u64 t, %1; cvt.u32.u64 %0, t; }" : "=r"(a) : "l"(p));
    return a;
}
__device__ __forceinline__ void cp16(uint32_t dst, const void* src) {
    asm volatile("cp.async.cg.shared.global [%0], [%1], 16;" :: "r"(dst), "l"(src) : "memory");
}
__device__ __forceinline__ void ldm_x4(uint32_t* r, uint32_t addr) {
    asm volatile("ldmatrix.sync.aligned.m8n8.x4.shared.b16 {%0,%1,%2,%3}, [%4];"
        : "=r"(r[0]), "=r"(r[1]), "=r"(r[2]), "=r"(r[3]) : "r"(addr));
}
__device__ __forceinline__ void mma_f16(float* c, const uint32_t* a, const uint32_t* b) {
    asm volatile(
        "mma.sync.aligned.m16n8k16.row.col.f32.f16.f16.f32 "
        "{%0,%1,%2,%3}, {%4,%5,%6,%7}, {%8,%9}, {%0,%1,%2,%3};"
        : "+f"(c[0]), "+f"(c[1]), "+f"(c[2]), "+f"(c[3])
        : "r"(a[0]), "r"(a[1]), "r"(a[2]), "r"(a[3]), "r"(b[0]), "r"(b[1]));
}

// ---------------- adjacency scan (standalone, low-reg, runs on s2) ----------
__global__ void __launch_bounds__(256)
scan_kernel(const float* __restrict__ adj) {
    int row  = blockIdx.x * 8 + (threadIdx.x >> 5);
    int lane = threadIdx.x & 31;
    const float4* ar = reinterpret_cast<const float4*>(adj + (size_t)row * NNODE);
    int* dst = g_nbr + (size_t)row * CAP;
    int base = 0;
    for (int j0 = 0; j0 < NNODE; j0 += 128) {
        float4 v = ar[(j0 >> 2) + lane];
        int h0 = v.x > 0.f, h1 = v.y > 0.f, h2 = v.z > 0.f, h3 = v.w > 0.f;
        int c4 = h0 + h1 + h2 + h3;
        int sc = c4;
        #pragma unroll
        for (int o = 1; o < 32; o <<= 1) {
            int nx = __shfl_up_sync(0xffffffffu, sc, o);
            if (lane >= o) sc += nx;
        }
        int pos = base + sc - c4;
        int jb = j0 + lane*4;
        if (h0) { if (pos < CAP) dst[pos] = jb;   pos++; }
        if (h1) { if (pos < CAP) dst[pos] = jb+1; pos++; }
        if (h2) { if (pos < CAP) dst[pos] = jb+2; pos++; }
        if (h3) { if (pos < CAP) dst[pos] = jb+3; pos++; }
        base += __shfl_sync(0xffffffffu, sc, 31);
    }
    if (lane == 0) g_cnt[row] = min(base, CAP);
}

// ---------------- prep: feats + weight transpose ----------
#define NB_FEATS 8192
#define NB_W     384

__global__ void __launch_bounds__(256)
prep_kernel(const int* __restrict__ x, const int* __restrict__ cue,
            const float* __restrict__ emb,
            const float* __restrict__ Wh, const float* __restrict__ Wq,
            const float* __restrict__ Wk, const float* __restrict__ Wv) {
    int bid = blockIdx.x;
    int t = threadIdx.x;
    if (bid < NB_FEATS) {
        int m = bid * 2 + (t >> 7);
        int d0 = (t & 127) * 2;
        int xi = x[m];
        float cuev = (float)cue[m];
        const float* er = emb + (size_t)xi * EMB;
        float v0 = (d0     < EMB) ? er[d0]   : cuev;
        float v1 = (d0 + 1 < EMB) ? er[d0+1] : cuev;
        *reinterpret_cast<__half2*>(&g_feats[(size_t)m*HID + d0]) = __floats2half2_rn(v0, v1);
    } else {
        int idx = (bid - NB_FEATS) * 256 + t;
        int n = idx >> 8, k = idx & 255;
        if (idx < 256*256)
            g_WhT[n*256 + k] = __float2half(Wh[k*256 + n]);
        float v = (n < 64) ? Wq[k*64 + n] : (n < 128) ? Wk[k*64 + (n-64)] : Wv[k*256 + (n-128)];
        g_WqkvT[n*256 + k] = __float2half(v);
    }
}

// ---------------- fp16 GEMM, ldmatrix + cp.async 2-stage, tile 128x128xBK64 --
#define TILE_HALVES (128*HPAD)
#define STAGE_HALVES (2*TILE_HALVES)
#define SMEM_BYTES  (2*STAGE_HALVES*2)

template<int MODE>
__global__ void __launch_bounds__(256, 2)
gemm_h_kernel(const __half* __restrict__ A, const __half* __restrict__ BT,
              __half* __restrict__ C, const float* __restrict__ bias,
              __half* __restrict__ qo, __half* __restrict__ kho, __half* __restrict__ vho) {
    extern __shared__ __half sm[];
    const int tid = threadIdx.x;
    const int lane = tid & 31, wid = tid >> 5;
    const int wm = (wid & 3) * 32;
    const int wn = (wid >> 2) * 64;
    const int m0 = blockIdx.y * 128;
    const int n0 = blockIdx.x * 128;
    const int r = lane >> 2, cql = lane & 3;
    const uint32_t sbase = smem_u32(sm);

    const uint32_t aBase = (uint32_t)((wm + (lane & 15)) * HPAD + ((lane >> 4) << 3));
    const uint32_t bBase = (uint32_t)((wn + (lane & 7) + ((lane >> 4) << 3)) * HPAD
                                      + (((lane >> 3) & 1) << 3));

    float acc[2][8][4];
    #pragma unroll
    for (int i = 0; i < 2; i++)
        #pragma unroll
        for (int j = 0; j < 8; j++)
            #pragma unroll
            for (int e = 0; e < 4; e++) acc[i][j][e] = 0.0f;

    auto stage = [&](int buf, int kt) {
        uint32_t dbase = sbase + (uint32_t)(buf * STAGE_HALVES) * 2u;
        #pragma unroll
        for (int i = 0; i < 4; i++) {
            int idx = tid + i*256;
            int row = idx >> 3, ck = (idx & 7) << 3;
            cp16(dbase + (uint32_t)(row*HPAD + ck)*2u,
                 A + (size_t)(m0+row)*KDIM + kt + ck);
        }
        #pragma unroll
        for (int i = 0; i < 4; i++) {
            int idx = tid + i*256;
            int row = idx >> 3, ck = (idx & 7) << 3;
            cp16(dbase + (uint32_t)(TILE_HALVES + row*HPAD + ck)*2u,
                 BT + (size_t)(n0+row)*KDIM + kt + ck);
        }
        asm volatile("cp.async.commit_group;" ::: "memory");
    };

    stage(0, 0);
    for (int c = 0; c < 4; c++) {
        asm volatile("cp.async.wait_group 0;" ::: "memory");
        __syncthreads();
        if (c < 3) stage((c+1) & 1, (c+1)*64);

        const uint32_t As = sbase + (uint32_t)((c & 1) * STAGE_HALVES) * 2u;
        const uint32_t Bs = As + (uint32_t)TILE_HALVES * 2u;

        #pragma unroll
        for (int k16 = 0; k16 < 4; k16++) {
            const uint32_t kk = k16 * 16;
            uint32_t a[2][4], b[8][2];
            #pragma unroll
            for (int i = 0; i < 2; i++)
                ldm_x4(a[i], As + (aBase + (uint32_t)(i*16*HPAD) + kk) * 2u);
            #pragma unroll
            for (int p = 0; p < 4; p++) {
                uint32_t rb[4];
                ldm_x4(rb, Bs + (bBase + (uint32_t)(p*16*HPAD) + kk) * 2u);
                b[2*p][0]   = rb[0]; b[2*p][1]   = rb[1];
                b[2*p+1][0] = rb[2]; b[2*p+1][1] = rb[3];
            }
            #pragma unroll
            for (int i = 0; i < 2; i++)
                #pragma unroll
                for (int j = 0; j < 8; j++)
                    mma_f16(acc[i][j], a[i], b[j]);
        }
        __syncthreads();
    }

    #pragma unroll
    for (int i = 0; i < 2; i++) {
        int row = m0 + wm + i*16 + r;
        #pragma unroll
        for (int j = 0; j < 8; j++) {
            int col = n0 + wn + j*8 + cql*2;
            float v0 = acc[i][j][0], v1 = acc[i][j][1];
            float v2 = acc[i][j][2], v3 = acc[i][j][3];
            if (MODE == 0) {
                float b0 = bias[col], b1 = bias[col+1];
                v0 = fmaxf(v0 + b0, 0.f); v1 = fmaxf(v1 + b1, 0.f);
                v2 = fmaxf(v2 + b0, 0.f); v3 = fmaxf(v3 + b1, 0.f);
                *reinterpret_cast<__half2*>(&C[(size_t)row*HID + col])     = __floats2half2_rn(v0, v1);
                *reinterpret_cast<__half2*>(&C[(size_t)(row+8)*HID + col]) = __floats2half2_rn(v2, v3);
            } else {
                if (col < 64) {
                    *reinterpret_cast<__half2*>(&qo[(size_t)row*ATN + col])     = __floats2half2_rn(v0, v1);
                    *reinterpret_cast<__half2*>(&qo[(size_t)(row+8)*ATN + col]) = __floats2half2_rn(v2, v3);
                } else if (col < 128) {
                    *reinterpret_cast<__half2*>(&kho[(size_t)row*ATN + col - 64])     = __floats2half2_rn(v0, v1);
                    *reinterpret_cast<__half2*>(&kho[(size_t)(row+8)*ATN + col - 64]) = __floats2half2_rn(v2, v3);
                } else {
                    *reinterpret_cast<__half2*>(&vho[(size_t)row*HID + col - 128])     = __floats2half2_rn(v0, v1);
                    *reinterpret_cast<__half2*>(&vho[(size_t)(row+8)*HID + col - 128]) = __floats2half2_rn(v2, v3);
                }
            }
        }
    }
}

// ---------------- sparse graph attention: warp/node, HFMA2 inner loops ------
template<int LAST>
__global__ void __launch_bounds__(256, 5)
attn_kernel(const __half* __restrict__ q, const __half* __restrict__ kh,
            const __half* __restrict__ vh, __half* __restrict__ hout,
            const float* __restrict__ gcb,
            const float* __restrict__ Wc, const float* __restrict__ bc,
            float* __restrict__ out) {
    const int wid = threadIdx.x >> 5, lane = threadIdx.x & 31;
    const int node = blockIdx.x * 8 + wid;
    __shared__ uint32_t qs[8][32];          // q row as raw half2
    __shared__ float ps[8][CPAD];
    __shared__ int   js[8][CPAD];
    __shared__ __align__(16) uint4 vring[8][8][32];

    const int cnt = g_cnt[node];
    float outv[8];

    if (cnt > 0) {
        qs[wid][lane] = reinterpret_cast<const uint32_t*>(q + (size_t)node*ATN)[lane];
        __syncwarp();

        const int* nl = g_nbr + (size_t)node * CAP;
        const __half2 hz = __float2half2_rn(0.0f);

        // logits: one neighbor per lane, half2 dot with fp32 final reduce
        for (int t0 = 0; t0 < cnt; t0 += 32) {
            int jn = t0 + lane;
            if (jn < cnt) {
                int j = nl[jn];
                js[wid][jn] = j;
                const uint4* kp = reinterpret_cast<const uint4*>(kh + (size_t)j*ATN);
                const uint4* qp = reinterpret_cast<const uint4*>(&qs[wid][0]);
                __half2 a0 = hz, a1 = hz, a2 = hz, a3 = hz;
                #pragma unroll
                for (int b = 0; b < 8; b++) {
                    uint4 kk = kp[b];
                    uint4 qq = qp[b];
                    const __half2* hk = reinterpret_cast<const __half2*>(&kk);
                    const __half2* hq = reinterpret_cast<const __half2*>(&qq);
                    a0 = __hfma2(hq[0], hk[0], a0);
                    a1 = __hfma2(hq[1], hk[1], a1);
                    a2 = __hfma2(hq[2], hk[2], a2);
                    a3 = __hfma2(hq[3], hk[3], a3);
                }
                float2 r0 = __half22float2(a0), r1 = __half22float2(a1);
                float2 r2 = __half22float2(a2), r3 = __half22float2(a3);
                ps[wid][jn] = ((r0.x + r0.y) + (r1.x + r1.y))
                            + ((r2.x + r2.y) + (r3.x + r3.y));
            }
        }
        __syncwarp();

        float mx = -1e30f;
        for (int jn = lane; jn < cnt; jn += 32) mx = fmaxf(mx, ps[wid][jn]);
        #pragma unroll
        for (int o = 16; o; o >>= 1) mx = fmaxf(mx, __shfl_xor_sync(0xffffffffu, mx, o));
        float sum = 0.0f;
        for (int jn = lane; jn < cnt; jn += 32) {
            float e = __expf(ps[wid][jn] - mx);
            ps[wid][jn] = e;
            sum += e;
        }
        #pragma unroll
        for (int o = 16; o; o >>= 1) sum += __shfl_xor_sync(0xffffffffu, sum, o);
        float sinv = 1.0f / sum;
        __syncwarp();

        // ---- V accumulation: groups of 4, half2 FMA, fp32 merge per group --
        const uint32_t ringb = smem_u32(&vring[wid][0][0]) + (uint32_t)lane * 16u;
        const int cm1 = cnt - 1;
        #pragma unroll
        for (int r = 0; r < 4; r++) {
            int idx = (r < cnt) ? r : cm1;
            cp16(ringb + (uint32_t)r * 512u, vh + (size_t)js[wid][idx]*HID + lane*8);
        }
        asm volatile("cp.async.commit_group;" ::: "memory");
        #pragma unroll
        for (int r = 4; r < 8; r++) {
            int idx = (r < cnt) ? r : cm1;
            cp16(ringb + (uint32_t)r * 512u, vh + (size_t)js[wid][idx]*HID + lane*8);
        }
        asm volatile("cp.async.commit_group;" ::: "memory");

        float acc[8] = {0,0,0,0,0,0,0,0};
        const int ng = (cnt + 3) >> 2;
        for (int g = 0; g < ng; g++) {
            asm volatile("cp.async.wait_group 1;" ::: "memory");
            const int base = g * 4;
            __half2 h0 = hz, h1 = hz, h2 = hz, h3 = hz;
            #pragma unroll
            for (int r = 0; r < 4; r++) {
                int row = base + r;
                float p = (row < cnt) ? ps[wid][row] : 0.0f;
                __half2 ph = __float2half2_rn(p);
                uint4 vv = vring[wid][row & 7][lane];
                const __half2* hp = reinterpret_cast<const __half2*>(&vv);
                h0 = __hfma2(ph, hp[0], h0);
                h1 = __hfma2(ph, hp[1], h1);
                h2 = __hfma2(ph, hp[2], h2);
                h3 = __hfma2(ph, hp[3], h3);
            }
            float2 f0 = __half22float2(h0), f1 = __half22float2(h1);
            float2 f2 = __half22float2(h2), f3 = __half22float2(h3);
            acc[0] += f0.x; acc[1] += f0.y; acc[2] += f1.x; acc[3] += f1.y;
            acc[4] += f2.x; acc[5] += f2.y; acc[6] += f3.x; acc[7] += f3.y;
            #pragma unroll
            for (int r = 0; r < 4; r++) {
                int row = base + 8 + r;
                int idx = (row < cnt) ? row : cm1;
                cp16(ringb + (uint32_t)(row & 7) * 512u, vh + (size_t)js[wid][idx]*HID + lane*8);
            }
            asm volatile("cp.async.commit_group;" ::: "memory");
        }

        #pragma unroll
        for (int e = 0; e < 8; e++) {
            float val = acc[e] * sinv + gcb[lane*8 + e];
            outv[e] = 1.0f / (1.0f + __expf(-val));
        }
    } else {
        #pragma unroll
        for (int e = 0; e < 8; e++)
            outv[e] = 1.0f / (1.0f + __expf(-gcb[lane*8 + e]));
    }

    if (LAST) {
        float a0 = 0.0f, a1 = 0.0f;
        #pragma unroll
        for (int e = 0; e < 8; e++) {
            int c = lane*8 + e;
            a0 = fmaf(outv[e], Wc[2*c],     a0);
            a1 = fmaf(outv[e], Wc[2*c + 1], a1);
        }
        #pragma unroll
        for (int o = 16; o; o >>= 1) {
            a0 += __shfl_xor_sync(0xffffffffu, a0, o);
            a1 += __shfl_xor_sync(0xffffffffu, a1, o);
        }
        if (lane == 0) {
            a0 += bc[0]; a1 += bc[1];
            float m = fmaxf(a0, a1);
            float e0 = __expf(a0 - m), e1 = __expf(a1 - m);
            float inv = 1.0f / (e0 + e1);
            out[node*2 + 0] = e0 * inv;
            out[node*2 + 1] = e1 * inv;
        }
    } else {
        __half2 ov[4];
        #pragma unroll
        for (int e = 0; e < 4; e++)
            ov[e] = __floats2half2_rn(outv[2*e], outv[2*e+1]);
        *reinterpret_cast<uint4*>(hout + (size_t)node*HID + lane*8) = *reinterpret_cast<uint4*>(ov);
    }
}

// ---------------- launch ----------------
extern "C" void kernel_launch(void* const* d_in, const int* in_sizes, int n_in,
                              void* d_out, int out_size) {
    const int*   x   = (const int*)  d_in[0];
    const int*   cue = (const int*)  d_in[1];
    const float* adj = (const float*)d_in[2];
    const float* emb = (const float*)d_in[3];
    const float* Wh  = (const float*)d_in[4];
    const float* bh  = (const float*)d_in[5];
    const float* Wq  = (const float*)d_in[6];
    const float* Wk  = (const float*)d_in[7];
    const float* Wv  = (const float*)d_in[8];
    const float* gcb = (const float*)d_in[9];
    const float* Wc  = (const float*)d_in[10];
    const float* bc  = (const float*)d_in[11];
    float* out = (float*)d_out;

    void *p_feats, *p_h0, *p_h1, *p_q, *p_kh, *p_vh, *p_WhT, *p_WqkvT;
    cudaGetSymbolAddress(&p_feats, g_feats);
    cudaGetSymbolAddress(&p_h0,    g_h0);
    cudaGetSymbolAddress(&p_h1,    g_h1);
    cudaGetSymbolAddress(&p_q,     g_q);
    cudaGetSymbolAddress(&p_kh,    g_kh);
    cudaGetSymbolAddress(&p_vh,    g_vh);
    cudaGetSymbolAddress(&p_WhT,   g_WhT);
    cudaGetSymbolAddress(&p_WqkvT, g_WqkvT);
    __half* feats = (__half*)p_feats;
    __half* h0    = (__half*)p_h0;
    __half* h1    = (__half*)p_h1;
    __half* qbuf  = (__half*)p_q;
    __half* khb   = (__half*)p_kh;
    __half* vhb   = (__half*)p_vh;
    __half* WhT   = (__half*)p_WhT;
    __half* WqkvT = (__half*)p_WqkvT;

    cudaFuncSetAttribute(gemm_h_kernel<0>, cudaFuncAttributeMaxDynamicSharedMemorySize, SMEM_BYTES);
    cudaFuncSetAttribute(gemm_h_kernel<1>, cudaFuncAttributeMaxDynamicSharedMemorySize, SMEM_BYTES);

    // ---- fork: adjacency scan on s2, concurrent with prep + gemm0 + qkv0 ----
    cudaEventRecord(g_evFork, 0);
    cudaStreamWaitEvent(g_s2, g_evFork, 0);
    scan_kernel<<<NNODE, 256, 0, g_s2>>>(adj);
    cudaEventRecord(g_evJoin, g_s2);

    prep_kernel<<<NB_FEATS + NB_W, 256>>>(x, cue, emb, Wh, Wq, Wk, Wv);
    gemm_h_kernel<0><<<dim3(2, 128), 256, SMEM_BYTES>>>(feats, WhT, h0, bh, nullptr, nullptr, nullptr);
    gemm_h_kernel<1><<<dim3(3, 128), 256, SMEM_BYTES>>>(h0, WqkvT, nullptr, nullptr, qbuf, khb, vhb);

    cudaStreamWaitEvent(0, g_evJoin, 0);
    attn_kernel<0><<<MTOT/8, 256>>>(qbuf, khb, vhb, h1, gcb, nullptr, nullptr, nullptr);

    gemm_h_kernel<1><<<dim3(3, 128), 256, SMEM_BYTES>>>(h1, WqkvT, nullptr, nullptr, qbuf, khb, vhb);
    attn_kernel<1><<<MTOT/8, 256>>>(qbuf, khb, vhb, nullptr, gcb, Wc, bc, out);
}

// round 14
// speedup vs baseline: 1.0971x; 1.0913x over previous
#include <cuda_runtime.h>
#include <cuda_fp16.h>
#include <cstdint>
#include <math.h>

// ---------------- problem constants ----------------
#define BATCH   8
#define NNODE   2048
#define MTOT    16384
#define HID     256
#define ATN     64
#define EMB     255
#define QKV     384
#define KDIM    256
#define CAP     64
#define CPAD    76
#define HPAD    72

// ---------------- device scratch ----------------
__device__ __align__(16) __half g_feats[MTOT*HID];
__device__ __align__(16) __half g_h0[MTOT*HID];
__device__ __align__(16) __half g_h1[MTOT*HID];
__device__ __align__(16) __half g_q[MTOT*ATN];
__device__ __align__(16) __half g_kh[MTOT*ATN];
__device__ __align__(16) __half g_vh[(size_t)MTOT*HID];
__device__ __align__(16) __half g_WhT[HID*KDIM];
__device__ __align__(16) __half g_WqkvT[QKV*KDIM];
__device__ int   g_nbr[(size_t)MTOT*CAP];
__device__ int   g_cnt[MTOT];

// ---------------- stream/event for fork-join ----------------
static cudaStream_t g_s2 = nullptr;
static cudaEvent_t  g_evFork = nullptr, g_evJoin = nullptr;
struct _StreamInit {
    _StreamInit() {
        cudaStreamCreateWithFlags(&g_s2, cudaStreamNonBlocking);
        cudaEventCreateWithFlags(&g_evFork, cudaEventDisableTiming);
        cudaEventCreateWithFlags(&g_evJoin, cudaEventDisableTiming);
    }
};
static _StreamInit _streamInit;

__device__ __forceinline__ uint32_t smem_u32(const void* p) {
    uint32_t a;
    asm("{ .reg .u64 t; cvta.to.shared.u64 t, %1; cvt.u32.u64 %0, t; }" : "=r"(a) : "l"(p));
    return a;
}
__device__ __forceinline__ void cp16(uint32_t dst, const void* src) {
    asm volatile("cp.async.cg.shared.global [%0], [%1], 16;" :: "r"(dst), "l"(src) : "memory");
}
__device__ __forceinline__ void ldm_x4(uint32_t* r, uint32_t addr) {
    asm volatile("ldmatrix.sync.aligned.m8n8.x4.shared.b16 {%0,%1,%2,%3}, [%4];"
        : "=r"(r[0]), "=r"(r[1]), "=r"(r[2]), "=r"(r[3]) : "r"(addr));
}
__device__ __forceinline__ void mma_f16(float* c, const uint32_t* a, const uint32_t* b) {
    asm volatile(
        "mma.sync.aligned.m16n8k16.row.col.f32.f16.f16.f32 "
        "{%0,%1,%2,%3}, {%4,%5,%6,%7}, {%8,%9}, {%0,%1,%2,%3};"
        : "+f"(c[0]), "+f"(c[1]), "+f"(c[2]), "+f"(c[3])
        : "r"(a[0]), "r"(a[1]), "r"(a[2]), "r"(a[3]), "r"(b[0]), "r"(b[1]));
}

// ---------------- adjacency scan (standalone, low-reg, runs on s2) ----------
__global__ void __launch_bounds__(256)
scan_kernel(const float* __restrict__ adj) {
    int row  = blockIdx.x * 8 + (threadIdx.x >> 5);
    int lane = threadIdx.x & 31;
    const float4* ar = reinterpret_cast<const float4*>(adj + (size_t)row * NNODE);
    int* dst = g_nbr + (size_t)row * CAP;
    int base = 0;
    for (int j0 = 0; j0 < NNODE; j0 += 128) {
        float4 v = ar[(j0 >> 2) + lane];
        int h0 = v.x > 0.f, h1 = v.y > 0.f, h2 = v.z > 0.f, h3 = v.w > 0.f;
        int c4 = h0 + h1 + h2 + h3;
        int sc = c4;
        #pragma unroll
        for (int o = 1; o < 32; o <<= 1) {
            int nx = __shfl_up_sync(0xffffffffu, sc, o);
            if (lane >= o) sc += nx;
        }
        int pos = base + sc - c4;
        int jb = j0 + lane*4;
        if (h0) { if (pos < CAP) dst[pos] = jb;   pos++; }
        if (h1) { if (pos < CAP) dst[pos] = jb+1; pos++; }
        if (h2) { if (pos < CAP) dst[pos] = jb+2; pos++; }
        if (h3) { if (pos < CAP) dst[pos] = jb+3; pos++; }
        base += __shfl_sync(0xffffffffu, sc, 31);
    }
    if (lane == 0) g_cnt[row] = min(base, CAP);
}

// ---------------- prep: feats + weight transpose ----------
#define NB_FEATS 8192
#define NB_W     384

__global__ void __launch_bounds__(256)
prep_kernel(const int* __restrict__ x, const int* __restrict__ cue,
            const float* __restrict__ emb,
            const float* __restrict__ Wh, const float* __restrict__ Wq,
            const float* __restrict__ Wk, const float* __restrict__ Wv) {
    int bid = blockIdx.x;
    int t = threadIdx.x;
    if (bid < NB_FEATS) {
        int m = bid * 2 + (t >> 7);
        int d0 = (t & 127) * 2;
        int xi = x[m];
        float cuev = (float)cue[m];
        const float* er = emb + (size_t)xi * EMB;
        float v0 = (d0     < EMB) ? er[d0]   : cuev;
        float v1 = (d0 + 1 < EMB) ? er[d0+1] : cuev;
        *reinterpret_cast<__half2*>(&g_feats[(size_t)m*HID + d0]) = __floats2half2_rn(v0, v1);
    } else {
        int idx = (bid - NB_FEATS) * 256 + t;
        int n = idx >> 8, k = idx & 255;
        if (idx < 256*256)
            g_WhT[n*256 + k] = __float2half(Wh[k*256 + n]);
        float v = (n < 64) ? Wq[k*64 + n] : (n < 128) ? Wk[k*64 + (n-64)] : Wv[k*256 + (n-128)];
        g_WqkvT[n*256 + k] = __float2half(v);
    }
}

// ---------------- fp16 GEMM, ldmatrix + cp.async 2-stage, tile 128x128xBK64 --
#define TILE_HALVES (128*HPAD)
#define STAGE_HALVES (2*TILE_HALVES)
#define SMEM_BYTES  (2*STAGE_HALVES*2)

template<int MODE>
__global__ void __launch_bounds__(256, 2)
gemm_h_kernel(const __half* __restrict__ A, const __half* __restrict__ BT,
              __half* __restrict__ C, const float* __restrict__ bias,
              __half* __restrict__ qo, __half* __restrict__ kho, __half* __restrict__ vho) {
    extern __shared__ __half sm[];
    const int tid = threadIdx.x;
    const int lane = tid & 31, wid = tid >> 5;
    const int wm = (wid & 3) * 32;
    const int wn = (wid >> 2) * 64;
    const int m0 = blockIdx.y * 128;
    const int n0 = blockIdx.x * 128;
    const int r = lane >> 2, cql = lane & 3;
    const uint32_t sbase = smem_u32(sm);

    const uint32_t aBase = (uint32_t)((wm + (lane & 15)) * HPAD + ((lane >> 4) << 3));
    const uint32_t bBase = (uint32_t)((wn + (lane & 7) + ((lane >> 4) << 3)) * HPAD
                                      + (((lane >> 3) & 1) << 3));

    float acc[2][8][4];
    #pragma unroll
    for (int i = 0; i < 2; i++)
        #pragma unroll
        for (int j = 0; j < 8; j++)
            #pragma unroll
            for (int e = 0; e < 4; e++) acc[i][j][e] = 0.0f;

    auto stage = [&](int buf, int kt) {
        uint32_t dbase = sbase + (uint32_t)(buf * STAGE_HALVES) * 2u;
        #pragma unroll
        for (int i = 0; i < 4; i++) {
            int idx = tid + i*256;
            int row = idx >> 3, ck = (idx & 7) << 3;
            cp16(dbase + (uint32_t)(row*HPAD + ck)*2u,
                 A + (size_t)(m0+row)*KDIM + kt + ck);
        }
        #pragma unroll
        for (int i = 0; i < 4; i++) {
            int idx = tid + i*256;
            int row = idx >> 3, ck = (idx & 7) << 3;
            cp16(dbase + (uint32_t)(TILE_HALVES + row*HPAD + ck)*2u,
                 BT + (size_t)(n0+row)*KDIM + kt + ck);
        }
        asm volatile("cp.async.commit_group;" ::: "memory");
    };

    stage(0, 0);
    for (int c = 0; c < 4; c++) {
        asm volatile("cp.async.wait_group 0;" ::: "memory");
        __syncthreads();
        if (c < 3) stage((c+1) & 1, (c+1)*64);

        const uint32_t As = sbase + (uint32_t)((c & 1) * STAGE_HALVES) * 2u;
        const uint32_t Bs = As + (uint32_t)TILE_HALVES * 2u;

        #pragma unroll
        for (int k16 = 0; k16 < 4; k16++) {
            const uint32_t kk = k16 * 16;
            uint32_t a[2][4], b[8][2];
            #pragma unroll
            for (int i = 0; i < 2; i++)
                ldm_x4(a[i], As + (aBase + (uint32_t)(i*16*HPAD) + kk) * 2u);
            #pragma unroll
            for (int p = 0; p < 4; p++) {
                uint32_t rb[4];
                ldm_x4(rb, Bs + (bBase + (uint32_t)(p*16*HPAD) + kk) * 2u);
                b[2*p][0]   = rb[0]; b[2*p][1]   = rb[1];
                b[2*p+1][0] = rb[2]; b[2*p+1][1] = rb[3];
            }
            #pragma unroll
            for (int i = 0; i < 2; i++)
                #pragma unroll
                for (int j = 0; j < 8; j++)
                    mma_f16(acc[i][j], a[i], b[j]);
        }
        __syncthreads();
    }

    #pragma unroll
    for (int i = 0; i < 2; i++) {
        int row = m0 + wm + i*16 + r;
        #pragma unroll
        for (int j = 0; j < 8; j++) {
            int col = n0 + wn + j*8 + cql*2;
            float v0 = acc[i][j][0], v1 = acc[i][j][1];
            float v2 = acc[i][j][2], v3 = acc[i][j][3];
            if (MODE == 0) {
                float b0 = bias[col], b1 = bias[col+1];
                v0 = fmaxf(v0 + b0, 0.f); v1 = fmaxf(v1 + b1, 0.f);
                v2 = fmaxf(v2 + b0, 0.f); v3 = fmaxf(v3 + b1, 0.f);
                *reinterpret_cast<__half2*>(&C[(size_t)row*HID + col])     = __floats2half2_rn(v0, v1);
                *reinterpret_cast<__half2*>(&C[(size_t)(row+8)*HID + col]) = __floats2half2_rn(v2, v3);
            } else {
                if (col < 64) {
                    *reinterpret_cast<__half2*>(&qo[(size_t)row*ATN + col])     = __floats2half2_rn(v0, v1);
                    *reinterpret_cast<__half2*>(&qo[(size_t)(row+8)*ATN + col]) = __floats2half2_rn(v2, v3);
                } else if (col < 128) {
                    *reinterpret_cast<__half2*>(&kho[(size_t)row*ATN + col - 64])     = __floats2half2_rn(v0, v1);
                    *reinterpret_cast<__half2*>(&kho[(size_t)(row+8)*ATN + col - 64]) = __floats2half2_rn(v2, v3);
                } else {
                    *reinterpret_cast<__half2*>(&vho[(size_t)row*HID + col - 128])     = __floats2half2_rn(v0, v1);
                    *reinterpret_cast<__half2*>(&vho[(size_t)(row+8)*HID + col - 128]) = __floats2half2_rn(v2, v3);
                }
            }
        }
    }
}

// ---------------- sparse graph attention: 4 lanes/neighbor logits + V ring --
template<int LAST>
__global__ void __launch_bounds__(256, 5)
attn_kernel(const __half* __restrict__ q, const __half* __restrict__ kh,
            const __half* __restrict__ vh, __half* __restrict__ hout,
            const float* __restrict__ gcb,
            const float* __restrict__ Wc, const float* __restrict__ bc,
            float* __restrict__ out) {
    const int wid = threadIdx.x >> 5, lane = threadIdx.x & 31;
    const int node = blockIdx.x * 8 + wid;
    const int sub = lane & 3;       // quarter of the 64-dim attention row
    const int grp = lane >> 2;      // neighbor slot within a pass of 8
    __shared__ float ps[8][CPAD];
    __shared__ int   js[8][CPAD];
    __shared__ __align__(16) uint4 vring[8][8][32];

    const int cnt = g_cnt[node];
    float outv[8];

    if (cnt > 0) {
        // q fragment for this lane's quarter (broadcast load, stays in regs)
        const uint4* qp = reinterpret_cast<const uint4*>(q + (size_t)node*ATN);
        uint4 qa = qp[sub*2], qb = qp[sub*2+1];
        const __half2* hqa = reinterpret_cast<const __half2*>(&qa);
        const __half2* hqb = reinterpret_cast<const __half2*>(&qb);

        const int* nl = g_nbr + (size_t)node * CAP;
        const __half2 hz = __float2half2_rn(0.0f);

        // logits: 8 neighbors per pass, 4 lanes each
        for (int t0 = 0; t0 < cnt; t0 += 8) {
            int jn = t0 + grp;
            int j = nl[(jn < cnt) ? jn : (cnt - 1)];
            const uint4* kp = reinterpret_cast<const uint4*>(kh + (size_t)j*ATN);
            uint4 ka = kp[sub*2], kb = kp[sub*2+1];
            const __half2* hka = reinterpret_cast<const __half2*>(&ka);
            const __half2* hkb = reinterpret_cast<const __half2*>(&kb);
            __half2 a = hz;
            #pragma unroll
            for (int e = 0; e < 4; e++) a = __hfma2(hqa[e], hka[e], a);
            #pragma unroll
            for (int e = 0; e < 4; e++) a = __hfma2(hqb[e], hkb[e], a);
            float2 f = __half22float2(a);
            float d = f.x + f.y;
            d += __shfl_xor_sync(0xffffffffu, d, 1);
            d += __shfl_xor_sync(0xffffffffu, d, 2);
            if (sub == 0 && jn < cnt) { ps[wid][jn] = d; js[wid][jn] = j; }
        }
        __syncwarp();

        float mx = -1e30f;
        for (int jn = lane; jn < cnt; jn += 32) mx = fmaxf(mx, ps[wid][jn]);
        #pragma unroll
        for (int o = 16; o; o >>= 1) mx = fmaxf(mx, __shfl_xor_sync(0xffffffffu, mx, o));
        float sum = 0.0f;
        for (int jn = lane; jn < cnt; jn += 32) {
            float e = __expf(ps[wid][jn] - mx);
            ps[wid][jn] = e;
            sum += e;
        }
        #pragma unroll
        for (int o = 16; o; o >>= 1) sum += __shfl_xor_sync(0xffffffffu, sum, o);
        float sinv = 1.0f / sum;
        __syncwarp();

        // ---- V accumulation: groups of 4, half2 FMA, fp32 merge per group --
        const uint32_t ringb = smem_u32(&vring[wid][0][0]) + (uint32_t)lane * 16u;
        const int cm1 = cnt - 1;
        #pragma unroll
        for (int r = 0; r < 4; r++) {
            int idx = (r < cnt) ? r : cm1;
            cp16(ringb + (uint32_t)r * 512u, vh + (size_t)js[wid][idx]*HID + lane*8);
        }
        asm volatile("cp.async.commit_group;" ::: "memory");
        #pragma unroll
        for (int r = 4; r < 8; r++) {
            int idx = (r < cnt) ? r : cm1;
            cp16(ringb + (uint32_t)r * 512u, vh + (size_t)js[wid][idx]*HID + lane*8);
        }
        asm volatile("cp.async.commit_group;" ::: "memory");

        float acc[8] = {0,0,0,0,0,0,0,0};
        const int ng = (cnt + 3) >> 2;
        for (int g = 0; g < ng; g++) {
            asm volatile("cp.async.wait_group 1;" ::: "memory");
            const int base = g * 4;
            __half2 h0 = hz, h1 = hz, h2 = hz, h3 = hz;
            #pragma unroll
            for (int r = 0; r < 4; r++) {
                int row = base + r;
                float p = (row < cnt) ? ps[wid][row] : 0.0f;
                __half2 ph = __float2half2_rn(p);
                uint4 vv = vring[wid][row & 7][lane];
                const __half2* hp = reinterpret_cast<const __half2*>(&vv);
                h0 = __hfma2(ph, hp[0], h0);
                h1 = __hfma2(ph, hp[1], h1);
                h2 = __hfma2(ph, hp[2], h2);
                h3 = __hfma2(ph, hp[3], h3);
            }
            float2 f0 = __half22float2(h0), f1 = __half22float2(h1);
            float2 f2 = __half22float2(h2), f3 = __half22float2(h3);
            acc[0] += f0.x; acc[1] += f0.y; acc[2] += f1.x; acc[3] += f1.y;
            acc[4] += f2.x; acc[5] += f2.y; acc[6] += f3.x; acc[7] += f3.y;
            #pragma unroll
            for (int r = 0; r < 4; r++) {
                int row = base + 8 + r;
                int idx = (row < cnt) ? row : cm1;
                cp16(ringb + (uint32_t)(row & 7) * 512u, vh + (size_t)js[wid][idx]*HID + lane*8);
            }
            asm volatile("cp.async.commit_group;" ::: "memory");
        }

        #pragma unroll
        for (int e = 0; e < 8; e++) {
            float val = acc[e] * sinv + gcb[lane*8 + e];
            outv[e] = 1.0f / (1.0f + __expf(-val));
        }
    } else {
        #pragma unroll
        for (int e = 0; e < 8; e++)
            outv[e] = 1.0f / (1.0f + __expf(-gcb[lane*8 + e]));
    }

    if (LAST) {
        float a0 = 0.0f, a1 = 0.0f;
        #pragma unroll
        for (int e = 0; e < 8; e++) {
            int c = lane*8 + e;
            a0 = fmaf(outv[e], Wc[2*c],     a0);
            a1 = fmaf(outv[e], Wc[2*c + 1], a1);
        }
        #pragma unroll
        for (int o = 16; o; o >>= 1) {
            a0 += __shfl_xor_sync(0xffffffffu, a0, o);
            a1 += __shfl_xor_sync(0xffffffffu, a1, o);
        }
        if (lane == 0) {
            a0 += bc[0]; a1 += bc[1];
            float m = fmaxf(a0, a1);
            float e0 = __expf(a0 - m), e1 = __expf(a1 - m);
            float inv = 1.0f / (e0 + e1);
            out[node*2 + 0] = e0 * inv;
            out[node*2 + 1] = e1 * inv;
        }
    } else {
        __half2 ov[4];
        #pragma unroll
        for (int e = 0; e < 4; e++)
            ov[e] = __floats2half2_rn(outv[2*e], outv[2*e+1]);
        *reinterpret_cast<uint4*>(hout + (size_t)node*HID + lane*8) = *reinterpret_cast<uint4*>(ov);
    }
}

// ---------------- launch ----------------
extern "C" void kernel_launch(void* const* d_in, const int* in_sizes, int n_in,
                              void* d_out, int out_size) {
    const int*   x   = (const int*)  d_in[0];
    const int*   cue = (const int*)  d_in[1];
    const float* adj = (const float*)d_in[2];
    const float* emb = (const float*)d_in[3];
    const float* Wh  = (const float*)d_in[4];
    const float* bh  = (const float*)d_in[5];
    const float* Wq  = (const float*)d_in[6];
    const float* Wk  = (const float*)d_in[7];
    const float* Wv  = (const float*)d_in[8];
    const float* gcb = (const float*)d_in[9];
    const float* Wc  = (const float*)d_in[10];
    const float* bc  = (const float*)d_in[11];
    float* out = (float*)d_out;

    void *p_feats, *p_h0, *p_h1, *p_q, *p_kh, *p_vh, *p_WhT, *p_WqkvT;
    cudaGetSymbolAddress(&p_feats, g_feats);
    cudaGetSymbolAddress(&p_h0,    g_h0);
    cudaGetSymbolAddress(&p_h1,    g_h1);
    cudaGetSymbolAddress(&p_q,     g_q);
    cudaGetSymbolAddress(&p_kh,    g_kh);
    cudaGetSymbolAddress(&p_vh,    g_vh);
    cudaGetSymbolAddress(&p_WhT,   g_WhT);
    cudaGetSymbolAddress(&p_WqkvT, g_WqkvT);
    __half* feats = (__half*)p_feats;
    __half* h0    = (__half*)p_h0;
    __half* h1    = (__half*)p_h1;
    __half* qbuf  = (__half*)p_q;
    __half* khb   = (__half*)p_kh;
    __half* vhb   = (__half*)p_vh;
    __half* WhT   = (__half*)p_WhT;
    __half* WqkvT = (__half*)p_WqkvT;

    cudaFuncSetAttribute(gemm_h_kernel<0>, cudaFuncAttributeMaxDynamicSharedMemorySize, SMEM_BYTES);
    cudaFuncSetAttribute(gemm_h_kernel<1>, cudaFuncAttributeMaxDynamicSharedMemorySize, SMEM_BYTES);

    // ---- fork: adjacency scan on s2, concurrent with prep + gemm0 + qkv0 ----
    cudaEventRecord(g_evFork, 0);
    cudaStreamWaitEvent(g_s2, g_evFork, 0);
    scan_kernel<<<NNODE, 256, 0, g_s2>>>(adj);
    cudaEventRecord(g_evJoin, g_s2);

    prep_kernel<<<NB_FEATS + NB_W, 256>>>(x, cue, emb, Wh, Wq, Wk, Wv);
    gemm_h_kernel<0><<<dim3(2, 128), 256, SMEM_BYTES>>>(feats, WhT, h0, bh, nullptr, nullptr, nullptr);
    gemm_h_kernel<1><<<dim3(3, 128), 256, SMEM_BYTES>>>(h0, WqkvT, nullptr, nullptr, qbuf, khb, vhb);

    cudaStreamWaitEvent(0, g_evJoin, 0);
    attn_kernel<0><<<MTOT/8, 256>>>(qbuf, khb, vhb, h1, gcb, nullptr, nullptr, nullptr);

    gemm_h_kernel<1><<<dim3(3, 128), 256, SMEM_BYTES>>>(h1, WqkvT, nullptr, nullptr, qbuf, khb, vhb);
    attn_kernel<1><<<MTOT/8, 256>>>(qbuf, khb, vhb, nullptr, gcb, Wc, bc, out);
}

// round 15
// speedup vs baseline: 1.1013x; 1.0038x over previous
#include <cuda_runtime.h>
#include <cuda_fp16.h>
#include <cstdint>
#include <math.h>

// ---------------- problem constants ----------------
#define BATCH   8
#define NNODE   2048
#define MTOT    16384
#define HID     256
#define ATN     64
#define EMB     255
#define QKV     384
#define KDIM    256
#define CAP     64
#define CPAD    76
#define HPAD    72

// ---------------- device scratch ----------------
__device__ __align__(16) __half g_feats[MTOT*HID];
__device__ __align__(16) __half g_h0[MTOT*HID];
__device__ __align__(16) __half g_h1[MTOT*HID];
__device__ __align__(16) __half g_q[MTOT*ATN];
__device__ __align__(16) __half g_kh[MTOT*ATN];
__device__ __align__(16) __half g_vh[(size_t)MTOT*HID];
__device__ __align__(16) __half g_WhT[HID*KDIM];
__device__ __align__(16) __half g_WqkvT[QKV*KDIM];
__device__ int   g_nbr[(size_t)MTOT*CAP];
__device__ int   g_cnt[MTOT];

__device__ __forceinline__ uint32_t smem_u32(const void* p) {
    uint32_t a;
    asm("{ .reg .u64 t; cvta.to.shared.u64 t, %1; cvt.u32.u64 %0, t; }" : "=r"(a) : "l"(p));
    return a;
}
__device__ __forceinline__ void cp16(uint32_t dst, const void* src) {
    asm volatile("cp.async.cg.shared.global [%0], [%1], 16;" :: "r"(dst), "l"(src) : "memory");
}
__device__ __forceinline__ void ldm_x4(uint32_t* r, uint32_t addr) {
    asm volatile("ldmatrix.sync.aligned.m8n8.x4.shared.b16 {%0,%1,%2,%3}, [%4];"
        : "=r"(r[0]), "=r"(r[1]), "=r"(r[2]), "=r"(r[3]) : "r"(addr));
}
__device__ __forceinline__ void mma_f16(float* c, const uint32_t* a, const uint32_t* b) {
    asm volatile(
        "mma.sync.aligned.m16n8k16.row.col.f32.f16.f16.f32 "
        "{%0,%1,%2,%3}, {%4,%5,%6,%7}, {%8,%9}, {%0,%1,%2,%3};"
        : "+f"(c[0]), "+f"(c[1]), "+f"(c[2]), "+f"(c[3])
        : "r"(a[0]), "r"(a[1]), "r"(a[2]), "r"(a[3]), "r"(b[0]), "r"(b[1]));
}

// ---------------- fused prep: adj scan + feats + weight transpose ----------
#define NB_NBR   2048
#define NB_FEATS 8192
#define NB_W     384

__global__ void __launch_bounds__(256)
prep_kernel(const float* __restrict__ adj,
            const int* __restrict__ x, const int* __restrict__ cue,
            const float* __restrict__ emb,
            const float* __restrict__ Wh, const float* __restrict__ Wq,
            const float* __restrict__ Wk, const float* __restrict__ Wv) {
    int bid = blockIdx.x;
    int t = threadIdx.x;
    if (bid < NB_NBR) {
        int row  = bid * 8 + (t >> 5);
        int lane = t & 31;
        const float4* ar = reinterpret_cast<const float4*>(adj + (size_t)row * NNODE);
        int* dst = g_nbr + (size_t)row * CAP;
        int base = 0;
        for (int j0 = 0; j0 < NNODE; j0 += 128) {
            float4 v = ar[(j0 >> 2) + lane];
            int h0 = v.x > 0.f, h1 = v.y > 0.f, h2 = v.z > 0.f, h3 = v.w > 0.f;
            int c4 = h0 + h1 + h2 + h3;
            int sc = c4;
            #pragma unroll
            for (int o = 1; o < 32; o <<= 1) {
                int nx = __shfl_up_sync(0xffffffffu, sc, o);
                if (lane >= o) sc += nx;
            }
            int pos = base + sc - c4;
            int jb = j0 + lane*4;
            if (h0) { if (pos < CAP) dst[pos] = jb;   pos++; }
            if (h1) { if (pos < CAP) dst[pos] = jb+1; pos++; }
            if (h2) { if (pos < CAP) dst[pos] = jb+2; pos++; }
            if (h3) { if (pos < CAP) dst[pos] = jb+3; pos++; }
            base += __shfl_sync(0xffffffffu, sc, 31);
        }
        if (lane == 0) g_cnt[row] = min(base, CAP);
    } else if (bid < NB_NBR + NB_FEATS) {
        int m = (bid - NB_NBR) * 2 + (t >> 7);
        int d0 = (t & 127) * 2;
        int xi = x[m];
        float cuev = (float)cue[m];
        const float* er = emb + (size_t)xi * EMB;
        float v0 = (d0     < EMB) ? er[d0]   : cuev;
        float v1 = (d0 + 1 < EMB) ? er[d0+1] : cuev;
        *reinterpret_cast<__half2*>(&g_feats[(size_t)m*HID + d0]) = __floats2half2_rn(v0, v1);
    } else {
        int idx = (bid - NB_NBR - NB_FEATS) * 256 + t;
        int n = idx >> 8, k = idx & 255;
        if (idx < 256*256)
            g_WhT[n*256 + k] = __float2half(Wh[k*256 + n]);
        float v = (n < 64) ? Wq[k*64 + n] : (n < 128) ? Wk[k*64 + (n-64)] : Wv[k*256 + (n-128)];
        g_WqkvT[n*256 + k] = __float2half(v);
    }
}

// ---------------- fp16 GEMM, ldmatrix + cp.async 3-stage, tile 128x128xBK64 --
#define TILE_HALVES (128*HPAD)
#define STAGE_HALVES (2*TILE_HALVES)
#define SMEM_BYTES  (3*STAGE_HALVES*2)       // 110592 B, 2 CTAs/SM

template<int MODE>
__global__ void __launch_bounds__(256, 2)
gemm_h_kernel(const __half* __restrict__ A, const __half* __restrict__ BT,
              __half* __restrict__ C, const float* __restrict__ bias,
              __half* __restrict__ qo, __half* __restrict__ kho, __half* __restrict__ vho) {
    extern __shared__ __half sm[];
    const int tid = threadIdx.x;
    const int lane = tid & 31, wid = tid >> 5;
    const int wm = (wid & 3) * 32;
    const int wn = (wid >> 2) * 64;
    const int m0 = blockIdx.y * 128;
    const int n0 = blockIdx.x * 128;
    const int r = lane >> 2, cql = lane & 3;
    const uint32_t sbase = smem_u32(sm);

    const uint32_t aBase = (uint32_t)((wm + (lane & 15)) * HPAD + ((lane >> 4) << 3));
    const uint32_t bBase = (uint32_t)((wn + (lane & 7) + ((lane >> 4) << 3)) * HPAD
                                      + (((lane >> 3) & 1) << 3));

    float acc[2][8][4];
    #pragma unroll
    for (int i = 0; i < 2; i++)
        #pragma unroll
        for (int j = 0; j < 8; j++)
            #pragma unroll
            for (int e = 0; e < 4; e++) acc[i][j][e] = 0.0f;

    auto stage = [&](int buf, int kt) {
        uint32_t dbase = sbase + (uint32_t)(buf * STAGE_HALVES) * 2u;
        #pragma unroll
        for (int i = 0; i < 4; i++) {
            int idx = tid + i*256;
            int row = idx >> 3, ck = (idx & 7) << 3;
            cp16(dbase + (uint32_t)(row*HPAD + ck)*2u,
                 A + (size_t)(m0+row)*KDIM + kt + ck);
        }
        #pragma unroll
        for (int i = 0; i < 4; i++) {
            int idx = tid + i*256;
            int row = idx >> 3, ck = (idx & 7) << 3;
            cp16(dbase + (uint32_t)(TILE_HALVES + row*HPAD + ck)*2u,
                 BT + (size_t)(n0+row)*KDIM + kt + ck);
        }
        asm volatile("cp.async.commit_group;" ::: "memory");
    };

    stage(0, 0);
    stage(1, 64);
    #pragma unroll
    for (int c = 0; c < 4; c++) {
        asm volatile("cp.async.wait_group 1;" ::: "memory");
        __syncthreads();
        if (c < 2) stage((c + 2) % 3, (c + 2) * 64);

        const uint32_t As = sbase + (uint32_t)((c % 3) * STAGE_HALVES) * 2u;
        const uint32_t Bs = As + (uint32_t)TILE_HALVES * 2u;

        #pragma unroll
        for (int k16 = 0; k16 < 4; k16++) {
            const uint32_t kk = k16 * 16;
            uint32_t a[2][4], b[8][2];
            #pragma unroll
            for (int i = 0; i < 2; i++)
                ldm_x4(a[i], As + (aBase + (uint32_t)(i*16*HPAD) + kk) * 2u);
            #pragma unroll
            for (int p = 0; p < 4; p++) {
                uint32_t rb[4];
                ldm_x4(rb, Bs + (bBase + (uint32_t)(p*16*HPAD) + kk) * 2u);
                b[2*p][0]   = rb[0]; b[2*p][1]   = rb[1];
                b[2*p+1][0] = rb[2]; b[2*p+1][1] = rb[3];
            }
            #pragma unroll
            for (int i = 0; i < 2; i++)
                #pragma unroll
                for (int j = 0; j < 8; j++)
                    mma_f16(acc[i][j], a[i], b[j]);
        }
    }

    #pragma unroll
    for (int i = 0; i < 2; i++) {
        int row = m0 + wm + i*16 + r;
        #pragma unroll
        for (int j = 0; j < 8; j++) {
            int col = n0 + wn + j*8 + cql*2;
            float v0 = acc[i][j][0], v1 = acc[i][j][1];
            float v2 = acc[i][j][2], v3 = acc[i][j][3];
            if (MODE == 0) {
                float b0 = bias[col], b1 = bias[col+1];
                v0 = fmaxf(v0 + b0, 0.f); v1 = fmaxf(v1 + b1, 0.f);
                v2 = fmaxf(v2 + b0, 0.f); v3 = fmaxf(v3 + b1, 0.f);
                *reinterpret_cast<__half2*>(&C[(size_t)row*HID + col])     = __floats2half2_rn(v0, v1);
                *reinterpret_cast<__half2*>(&C[(size_t)(row+8)*HID + col]) = __floats2half2_rn(v2, v3);
            } else {
                if (col < 64) {
                    *reinterpret_cast<__half2*>(&qo[(size_t)row*ATN + col])     = __floats2half2_rn(v0, v1);
                    *reinterpret_cast<__half2*>(&qo[(size_t)(row+8)*ATN + col]) = __floats2half2_rn(v2, v3);
                } else if (col < 128) {
                    *reinterpret_cast<__half2*>(&kho[(size_t)row*ATN + col - 64])     = __floats2half2_rn(v0, v1);
                    *reinterpret_cast<__half2*>(&kho[(size_t)(row+8)*ATN + col - 64]) = __floats2half2_rn(v2, v3);
                } else {
                    *reinterpret_cast<__half2*>(&vho[(size_t)row*HID + col - 128])     = __floats2half2_rn(v0, v1);
                    *reinterpret_cast<__half2*>(&vho[(size_t)(row+8)*HID + col - 128]) = __floats2half2_rn(v2, v3);
                }
            }
        }
    }
}

// ---------------- sparse graph attention: 4 lanes/neighbor logits + V ring --
template<int LAST>
__global__ void __launch_bounds__(256, 5)
attn_kernel(const __half* __restrict__ q, const __half* __restrict__ kh,
            const __half* __restrict__ vh, __half* __restrict__ hout,
            const float* __restrict__ gcb,
            const float* __restrict__ Wc, const float* __restrict__ bc,
            float* __restrict__ out) {
    const int wid = threadIdx.x >> 5, lane = threadIdx.x & 31;
    const int node = blockIdx.x * 8 + wid;
    const int sub = lane & 3;
    const int grp = lane >> 2;
    __shared__ float ps[8][CPAD];
    __shared__ int   js[8][CPAD];
    __shared__ __align__(16) uint4 vring[8][8][32];

    const int cnt = g_cnt[node];
    float outv[8];

    if (cnt > 0) {
        const uint4* qp = reinterpret_cast<const uint4*>(q + (size_t)node*ATN);
        uint4 qa = qp[sub*2], qb = qp[sub*2+1];
        const __half2* hqa = reinterpret_cast<const __half2*>(&qa);
        const __half2* hqb = reinterpret_cast<const __half2*>(&qb);

        const int* nl = g_nbr + (size_t)node * CAP;
        const __half2 hz = __float2half2_rn(0.0f);

        for (int t0 = 0; t0 < cnt; t0 += 8) {
            int jn = t0 + grp;
            int j = nl[(jn < cnt) ? jn : (cnt - 1)];
            const uint4* kp = reinterpret_cast<const uint4*>(kh + (size_t)j*ATN);
            uint4 ka = kp[sub*2], kb = kp[sub*2+1];
            const __half2* hka = reinterpret_cast<const __half2*>(&ka);
            const __half2* hkb = reinterpret_cast<const __half2*>(&kb);
            __half2 a = hz;
            #pragma unroll
            for (int e = 0; e < 4; e++) a = __hfma2(hqa[e], hka[e], a);
            #pragma unroll
            for (int e = 0; e < 4; e++) a = __hfma2(hqb[e], hkb[e], a);
            float2 f = __half22float2(a);
            float d = f.x + f.y;
            d += __shfl_xor_sync(0xffffffffu, d, 1);
            d += __shfl_xor_sync(0xffffffffu, d, 2);
            if (sub == 0 && jn < cnt) { ps[wid][jn] = d; js[wid][jn] = j; }
        }
        __syncwarp();

        float mx = -1e30f;
        for (int jn = lane; jn < cnt; jn += 32) mx = fmaxf(mx, ps[wid][jn]);
        #pragma unroll
        for (int o = 16; o; o >>= 1) mx = fmaxf(mx, __shfl_xor_sync(0xffffffffu, mx, o));
        float sum = 0.0f;
        for (int jn = lane; jn < cnt; jn += 32) {
            float e = __expf(ps[wid][jn] - mx);
            ps[wid][jn] = e;
            sum += e;
        }
        #pragma unroll
        for (int o = 16; o; o >>= 1) sum += __shfl_xor_sync(0xffffffffu, sum, o);
        float sinv = 1.0f / sum;
        __syncwarp();

        const uint32_t ringb = smem_u32(&vring[wid][0][0]) + (uint32_t)lane * 16u;
        const int cm1 = cnt - 1;
        #pragma unroll
        for (int r = 0; r < 4; r++) {
            int idx = (r < cnt) ? r : cm1;
            cp16(ringb + (uint32_t)r * 512u, vh + (size_t)js[wid][idx]*HID + lane*8);
        }
        asm volatile("cp.async.commit_group;" ::: "memory");
        #pragma unroll
        for (int r = 4; r < 8; r++) {
            int idx = (r < cnt) ? r : cm1;
            cp16(ringb + (uint32_t)r * 512u, vh + (size_t)js[wid][idx]*HID + lane*8);
        }
        asm volatile("cp.async.commit_group;" ::: "memory");

        float acc[8] = {0,0,0,0,0,0,0,0};
        const int ng = (cnt + 3) >> 2;
        for (int g = 0; g < ng; g++) {
            asm volatile("cp.async.wait_group 1;" ::: "memory");
            const int base = g * 4;
            __half2 h0 = hz, h1 = hz, h2 = hz, h3 = hz;
            #pragma unroll
            for (int r = 0; r < 4; r++) {
                int row = base + r;
                float p = (row < cnt) ? ps[wid][row] : 0.0f;
                __half2 ph = __float2half2_rn(p);
                uint4 vv = vring[wid][row & 7][lane];
                const __half2* hp = reinterpret_cast<const __half2*>(&vv);
                h0 = __hfma2(ph, hp[0], h0);
                h1 = __hfma2(ph, hp[1], h1);
                h2 = __hfma2(ph, hp[2], h2);
                h3 = __hfma2(ph, hp[3], h3);
            }
            float2 f0 = __half22float2(h0), f1 = __half22float2(h1);
            float2 f2 = __half22float2(h2), f3 = __half22float2(h3);
            acc[0] += f0.x; acc[1] += f0.y; acc[2] += f1.x; acc[3] += f1.y;
            acc[4] += f2.x; acc[5] += f2.y; acc[6] += f3.x; acc[7] += f3.y;
            #pragma unroll
            for (int r = 0; r < 4; r++) {
                int row = base + 8 + r;
                int idx = (row < cnt) ? row : cm1;
                cp16(ringb + (uint32_t)(row & 7) * 512u, vh + (size_t)js[wid][idx]*HID + lane*8);
            }
            asm volatile("cp.async.commit_group;" ::: "memory");
        }

        #pragma unroll
        for (int e = 0; e < 8; e++) {
            float val = acc[e] * sinv + gcb[lane*8 + e];
            outv[e] = 1.0f / (1.0f + __expf(-val));
        }
    } else {
        #pragma unroll
        for (int e = 0; e < 8; e++)
            outv[e] = 1.0f / (1.0f + __expf(-gcb[lane*8 + e]));
    }

    if (LAST) {
        float a0 = 0.0f, a1 = 0.0f;
        #pragma unroll
        for (int e = 0; e < 8; e++) {
            int c = lane*8 + e;
            a0 = fmaf(outv[e], Wc[2*c],     a0);
            a1 = fmaf(outv[e], Wc[2*c + 1], a1);
        }
        #pragma unroll
        for (int o = 16; o; o >>= 1) {
            a0 += __shfl_xor_sync(0xffffffffu, a0, o);
            a1 += __shfl_xor_sync(0xffffffffu, a1, o);
        }
        if (lane == 0) {
            a0 += bc[0]; a1 += bc[1];
            float m = fmaxf(a0, a1);
            float e0 = __expf(a0 - m), e1 = __expf(a1 - m);
            float inv = 1.0f / (e0 + e1);
            out[node*2 + 0] = e0 * inv;
            out[node*2 + 1] = e1 * inv;
        }
    } else {
        __half2 ov[4];
        #pragma unroll
        for (int e = 0; e < 4; e++)
            ov[e] = __floats2half2_rn(outv[2*e], outv[2*e+1]);
        *reinterpret_cast<uint4*>(hout + (size_t)node*HID + lane*8) = *reinterpret_cast<uint4*>(ov);
    }
}

// ---------------- launch ----------------
extern "C" void kernel_launch(void* const* d_in, const int* in_sizes, int n_in,
                              void* d_out, int out_size) {
    const int*   x   = (const int*)  d_in[0];
    const int*   cue = (const int*)  d_in[1];
    const float* adj = (const float*)d_in[2];
    const float* emb = (const float*)d_in[3];
    const float* Wh  = (const float*)d_in[4];
    const float* bh  = (const float*)d_in[5];
    const float* Wq  = (const float*)d_in[6];
    const float* Wk  = (const float*)d_in[7];
    const float* Wv  = (const float*)d_in[8];
    const float* gcb = (const float*)d_in[9];
    const float* Wc  = (const float*)d_in[10];
    const float* bc  = (const float*)d_in[11];
    float* out = (float*)d_out;

    void *p_feats, *p_h0, *p_h1, *p_q, *p_kh, *p_vh, *p_WhT, *p_WqkvT;
    cudaGetSymbolAddress(&p_feats, g_feats);
    cudaGetSymbolAddress(&p_h0,    g_h0);
    cudaGetSymbolAddress(&p_h1,    g_h1);
    cudaGetSymbolAddress(&p_q,     g_q);
    cudaGetSymbolAddress(&p_kh,    g_kh);
    cudaGetSymbolAddress(&p_vh,    g_vh);
    cudaGetSymbolAddress(&p_WhT,   g_WhT);
    cudaGetSymbolAddress(&p_WqkvT, g_WqkvT);
    __half* feats = (__half*)p_feats;
    __half* h0    = (__half*)p_h0;
    __half* h1    = (__half*)p_h1;
    __half* qbuf  = (__half*)p_q;
    __half* khb   = (__half*)p_kh;
    __half* vhb   = (__half*)p_vh;
    __half* WhT   = (__half*)p_WhT;
    __half* WqkvT = (__half*)p_WqkvT;

    cudaFuncSetAttribute(gemm_h_kernel<0>, cudaFuncAttributeMaxDynamicSharedMemorySize, SMEM_BYTES);
    cudaFuncSetAttribute(gemm_h_kernel<1>, cudaFuncAttributeMaxDynamicSharedMemorySize, SMEM_BYTES);

    prep_kernel<<<NB_NBR + NB_FEATS + NB_W, 256>>>(adj, x, cue, emb, Wh, Wq, Wk, Wv);

    gemm_h_kernel<0><<<dim3(2, 128), 256, SMEM_BYTES>>>(feats, WhT, h0, bh, nullptr, nullptr, nullptr);

    // layer 0
    gemm_h_kernel<1><<<dim3(3, 128), 256, SMEM_BYTES>>>(h0, WqkvT, nullptr, nullptr, qbuf, khb, vhb);
    attn_kernel<0><<<MTOT/8, 256>>>(qbuf, khb, vhb, h1, gcb, nullptr, nullptr, nullptr);

    // layer 1 + fused classifier
    gemm_h_kernel<1><<<dim3(3, 128), 256, SMEM_BYTES>>>(h1, WqkvT, nullptr, nullptr, qbuf, khb, vhb);
    attn_kernel<1><<<MTOT/8, 256>>>(qbuf, khb, vhb, nullptr, gcb, Wc, bc, out);
}

// round 16
// speedup vs baseline: 1.1031x; 1.0017x over previous
#include <cuda_runtime.h>
#include <cuda_fp16.h>
#include <cstdint>
#include <math.h>

// ---------------- problem constants ----------------
#define BATCH   8
#define NNODE   2048
#define MTOT    16384
#define HID     256
#define ATN     64
#define EMB     255
#define QKV     384
#define KDIM    256
#define CAP     64
#define CPAD    68
#define HPAD    72

// ---------------- device scratch ----------------
__device__ __align__(16) __half g_feats[MTOT*HID];
__device__ __align__(16) __half g_h0[MTOT*HID];
__device__ __align__(16) __half g_h1[MTOT*HID];
__device__ __align__(16) __half g_q[MTOT*ATN];
__device__ __align__(16) __half g_kh[MTOT*ATN];
__device__ __align__(16) __half g_vh[(size_t)MTOT*HID];
__device__ __align__(16) __half g_WhT[HID*KDIM];
__device__ __align__(16) __half g_WqkvT[QKV*KDIM];
__device__ int   g_nbr[(size_t)MTOT*CAP];
__device__ int   g_cnt[MTOT];

__device__ __forceinline__ uint32_t smem_u32(const void* p) {
    uint32_t a;
    asm("{ .reg .u64 t; cvta.to.shared.u64 t, %1; cvt.u32.u64 %0, t; }" : "=r"(a) : "l"(p));
    return a;
}
__device__ __forceinline__ void cp16(uint32_t dst, const void* src) {
    asm volatile("cp.async.cg.shared.global [%0], [%1], 16;" :: "r"(dst), "l"(src) : "memory");
}
__device__ __forceinline__ void ldm_x4(uint32_t* r, uint32_t addr) {
    asm volatile("ldmatrix.sync.aligned.m8n8.x4.shared.b16 {%0,%1,%2,%3}, [%4];"
        : "=r"(r[0]), "=r"(r[1]), "=r"(r[2]), "=r"(r[3]) : "r"(addr));
}
__device__ __forceinline__ void mma_f16(float* c, const uint32_t* a, const uint32_t* b) {
    asm volatile(
        "mma.sync.aligned.m16n8k16.row.col.f32.f16.f16.f32 "
        "{%0,%1,%2,%3}, {%4,%5,%6,%7}, {%8,%9}, {%0,%1,%2,%3};"
        : "+f"(c[0]), "+f"(c[1]), "+f"(c[2]), "+f"(c[3])
        : "r"(a[0]), "r"(a[1]), "r"(a[2]), "r"(a[3]), "r"(b[0]), "r"(b[1]));
}

// ---------------- fused prep: adj scan + feats + weight transpose ----------
#define NB_NBR   2048
#define NB_FEATS 8192
#define NB_W     384

__global__ void __launch_bounds__(256)
prep_kernel(const float* __restrict__ adj,
            const int* __restrict__ x, const int* __restrict__ cue,
            const float* __restrict__ emb,
            const float* __restrict__ Wh, const float* __restrict__ Wq,
            const float* __restrict__ Wk, const float* __restrict__ Wv) {
    int bid = blockIdx.x;
    int t = threadIdx.x;
    if (bid < NB_NBR) {
        int row  = bid * 8 + (t >> 5);
        int lane = t & 31;
        const float4* ar = reinterpret_cast<const float4*>(adj + (size_t)row * NNODE);
        int* dst = g_nbr + (size_t)row * CAP;
        int base = 0;
        for (int j0 = 0; j0 < NNODE; j0 += 128) {
            float4 v = ar[(j0 >> 2) + lane];
            int h0 = v.x > 0.f, h1 = v.y > 0.f, h2 = v.z > 0.f, h3 = v.w > 0.f;
            int c4 = h0 + h1 + h2 + h3;
            int sc = c4;
            #pragma unroll
            for (int o = 1; o < 32; o <<= 1) {
                int nx = __shfl_up_sync(0xffffffffu, sc, o);
                if (lane >= o) sc += nx;
            }
            int pos = base + sc - c4;
            int jb = j0 + lane*4;
            if (h0) { if (pos < CAP) dst[pos] = jb;   pos++; }
            if (h1) { if (pos < CAP) dst[pos] = jb+1; pos++; }
            if (h2) { if (pos < CAP) dst[pos] = jb+2; pos++; }
            if (h3) { if (pos < CAP) dst[pos] = jb+3; pos++; }
            base += __shfl_sync(0xffffffffu, sc, 31);
        }
        if (lane == 0) g_cnt[row] = min(base, CAP);
    } else if (bid < NB_NBR + NB_FEATS) {
        int m = (bid - NB_NBR) * 2 + (t >> 7);
        int d0 = (t & 127) * 2;
        int xi = x[m];
        float cuev = (float)cue[m];
        const float* er = emb + (size_t)xi * EMB;
        float v0 = (d0     < EMB) ? er[d0]   : cuev;
        float v1 = (d0 + 1 < EMB) ? er[d0+1] : cuev;
        *reinterpret_cast<__half2*>(&g_feats[(size_t)m*HID + d0]) = __floats2half2_rn(v0, v1);
    } else {
        int idx = (bid - NB_NBR - NB_FEATS) * 256 + t;
        int n = idx >> 8, k = idx & 255;
        if (idx < 256*256)
            g_WhT[n*256 + k] = __float2half(Wh[k*256 + n]);
        float v = (n < 64) ? Wq[k*64 + n] : (n < 128) ? Wk[k*64 + (n-64)] : Wv[k*256 + (n-128)];
        g_WqkvT[n*256 + k] = __float2half(v);
    }
}

// ---------------- fp16 GEMM, ldmatrix + cp.async 3-stage, tile 128x128xBK64 --
#define TILE_HALVES (128*HPAD)
#define STAGE_HALVES (2*TILE_HALVES)
#define SMEM_BYTES  (3*STAGE_HALVES*2)

template<int MODE>
__global__ void __launch_bounds__(256, 2)
gemm_h_kernel(const __half* __restrict__ A, const __half* __restrict__ BT,
              __half* __restrict__ C, const float* __restrict__ bias,
              __half* __restrict__ qo, __half* __restrict__ kho, __half* __restrict__ vho) {
    extern __shared__ __half sm[];
    const int tid = threadIdx.x;
    const int lane = tid & 31, wid = tid >> 5;
    const int wm = (wid & 3) * 32;
    const int wn = (wid >> 2) * 64;
    const int m0 = blockIdx.y * 128;
    const int n0 = blockIdx.x * 128;
    const int r = lane >> 2, cql = lane & 3;
    const uint32_t sbase = smem_u32(sm);

    const uint32_t aBase = (uint32_t)((wm + (lane & 15)) * HPAD + ((lane >> 4) << 3));
    const uint32_t bBase = (uint32_t)((wn + (lane & 7) + ((lane >> 4) << 3)) * HPAD
                                      + (((lane >> 3) & 1) << 3));

    float acc[2][8][4];
    #pragma unroll
    for (int i = 0; i < 2; i++)
        #pragma unroll
        for (int j = 0; j < 8; j++)
            #pragma unroll
            for (int e = 0; e < 4; e++) acc[i][j][e] = 0.0f;

    auto stage = [&](int buf, int kt) {
        uint32_t dbase = sbase + (uint32_t)(buf * STAGE_HALVES) * 2u;
        #pragma unroll
        for (int i = 0; i < 4; i++) {
            int idx = tid + i*256;
            int row = idx >> 3, ck = (idx & 7) << 3;
            cp16(dbase + (uint32_t)(row*HPAD + ck)*2u,
                 A + (size_t)(m0+row)*KDIM + kt + ck);
        }
        #pragma unroll
        for (int i = 0; i < 4; i++) {
            int idx = tid + i*256;
            int row = idx >> 3, ck = (idx & 7) << 3;
            cp16(dbase + (uint32_t)(TILE_HALVES + row*HPAD + ck)*2u,
                 BT + (size_t)(n0+row)*KDIM + kt + ck);
        }
        asm volatile("cp.async.commit_group;" ::: "memory");
    };

    stage(0, 0);
    stage(1, 64);
    #pragma unroll
    for (int c = 0; c < 4; c++) {
        asm volatile("cp.async.wait_group 1;" ::: "memory");
        __syncthreads();
        if (c < 2) stage((c + 2) % 3, (c + 2) * 64);

        const uint32_t As = sbase + (uint32_t)((c % 3) * STAGE_HALVES) * 2u;
        const uint32_t Bs = As + (uint32_t)TILE_HALVES * 2u;

        #pragma unroll
        for (int k16 = 0; k16 < 4; k16++) {
            const uint32_t kk = k16 * 16;
            uint32_t a[2][4], b[8][2];
            #pragma unroll
            for (int i = 0; i < 2; i++)
                ldm_x4(a[i], As + (aBase + (uint32_t)(i*16*HPAD) + kk) * 2u);
            #pragma unroll
            for (int p = 0; p < 4; p++) {
                uint32_t rb[4];
                ldm_x4(rb, Bs + (bBase + (uint32_t)(p*16*HPAD) + kk) * 2u);
                b[2*p][0]   = rb[0]; b[2*p][1]   = rb[1];
                b[2*p+1][0] = rb[2]; b[2*p+1][1] = rb[3];
            }
            #pragma unroll
            for (int i = 0; i < 2; i++)
                #pragma unroll
                for (int j = 0; j < 8; j++)
                    mma_f16(acc[i][j], a[i], b[j]);
        }
    }

    #pragma unroll
    for (int i = 0; i < 2; i++) {
        int row = m0 + wm + i*16 + r;
        #pragma unroll
        for (int j = 0; j < 8; j++) {
            int col = n0 + wn + j*8 + cql*2;
            float v0 = acc[i][j][0], v1 = acc[i][j][1];
            float v2 = acc[i][j][2], v3 = acc[i][j][3];
            if (MODE == 0) {
                float b0 = bias[col], b1 = bias[col+1];
                v0 = fmaxf(v0 + b0, 0.f); v1 = fmaxf(v1 + b1, 0.f);
                v2 = fmaxf(v2 + b0, 0.f); v3 = fmaxf(v3 + b1, 0.f);
                *reinterpret_cast<__half2*>(&C[(size_t)row*HID + col])     = __floats2half2_rn(v0, v1);
                *reinterpret_cast<__half2*>(&C[(size_t)(row+8)*HID + col]) = __floats2half2_rn(v2, v3);
            } else {
                if (col < 64) {
                    *reinterpret_cast<__half2*>(&qo[(size_t)row*ATN + col])     = __floats2half2_rn(v0, v1);
                    *reinterpret_cast<__half2*>(&qo[(size_t)(row+8)*ATN + col]) = __floats2half2_rn(v2, v3);
                } else if (col < 128) {
                    *reinterpret_cast<__half2*>(&kho[(size_t)row*ATN + col - 64])     = __floats2half2_rn(v0, v1);
                    *reinterpret_cast<__half2*>(&kho[(size_t)(row+8)*ATN + col - 64]) = __floats2half2_rn(v2, v3);
                } else {
                    *reinterpret_cast<__half2*>(&vho[(size_t)row*HID + col - 128])     = __floats2half2_rn(v0, v1);
                    *reinterpret_cast<__half2*>(&vho[(size_t)(row+8)*HID + col - 128]) = __floats2half2_rn(v2, v3);
                }
            }
        }
    }
}

// ---------------- sparse graph attention: 4 lanes/neighbor logits + V ring --
template<int LAST>
__global__ void __launch_bounds__(256, 6)
attn_kernel(const __half* __restrict__ q, const __half* __restrict__ kh,
            const __half* __restrict__ vh, __half* __restrict__ hout,
            const float* __restrict__ gcb,
            const float* __restrict__ Wc, const float* __restrict__ bc,
            float* __restrict__ out) {
    const int wid = threadIdx.x >> 5, lane = threadIdx.x & 31;
    const int node = blockIdx.x * 8 + wid;
    const int sub = lane & 3;
    const int grp = lane >> 2;
    __shared__ float ps[8][CPAD];
    __shared__ int   js[8][CPAD];
    __shared__ __align__(16) uint4 vring[8][8][32];

    const int cnt = g_cnt[node];
    float outv[8];

    if (cnt > 0) {
        const uint4* qp = reinterpret_cast<const uint4*>(q + (size_t)node*ATN);
        uint4 qa = qp[sub*2], qb = qp[sub*2+1];
        const __half2* hqa = reinterpret_cast<const __half2*>(&qa);
        const __half2* hqb = reinterpret_cast<const __half2*>(&qb);

        const int* nl = g_nbr + (size_t)node * CAP;
        const __half2 hz = __float2half2_rn(0.0f);

        for (int t0 = 0; t0 < cnt; t0 += 8) {
            int jn = t0 + grp;
            int j = nl[(jn < cnt) ? jn : (cnt - 1)];
            const uint4* kp = reinterpret_cast<const uint4*>(kh + (size_t)j*ATN);
            uint4 ka = kp[sub*2], kb = kp[sub*2+1];
            const __half2* hka = reinterpret_cast<const __half2*>(&ka);
            const __half2* hkb = reinterpret_cast<const __half2*>(&kb);
            __half2 a = hz;
            #pragma unroll
            for (int e = 0; e < 4; e++) a = __hfma2(hqa[e], hka[e], a);
            #pragma unroll
            for (int e = 0; e < 4; e++) a = __hfma2(hqb[e], hkb[e], a);
            float2 f = __half22float2(a);
            float d = f.x + f.y;
            d += __shfl_xor_sync(0xffffffffu, d, 1);
            d += __shfl_xor_sync(0xffffffffu, d, 2);
            if (sub == 0 && jn < cnt) { ps[wid][jn] = d; js[wid][jn] = j; }
        }
        __syncwarp();

        float mx = -1e30f;
        for (int jn = lane; jn < cnt; jn += 32) mx = fmaxf(mx, ps[wid][jn]);
        #pragma unroll
        for (int o = 16; o; o >>= 1) mx = fmaxf(mx, __shfl_xor_sync(0xffffffffu, mx, o));
        float sum = 0.0f;
        for (int jn = lane; jn < cnt; jn += 32) {
            float e = __expf(ps[wid][jn] - mx);
            ps[wid][jn] = e;
            sum += e;
        }
        #pragma unroll
        for (int o = 16; o; o >>= 1) sum += __shfl_xor_sync(0xffffffffu, sum, o);
        float sinv = 1.0f / sum;
        __syncwarp();

        const uint32_t ringb = smem_u32(&vring[wid][0][0]) + (uint32_t)lane * 16u;
        const int cm1 = cnt - 1;
        #pragma unroll
        for (int r = 0; r < 4; r++) {
            int idx = (r < cnt) ? r : cm1;
            cp16(ringb + (uint32_t)r * 512u, vh + (size_t)js[wid][idx]*HID + lane*8);
        }
        asm volatile("cp.async.commit_group;" ::: "memory");
        #pragma unroll
        for (int r = 4; r < 8; r++) {
            int idx = (r < cnt) ? r : cm1;
            cp16(ringb + (uint32_t)r * 512u, vh + (size_t)js[wid][idx]*HID + lane*8);
        }
        asm volatile("cp.async.commit_group;" ::: "memory");

        float acc[8] = {0,0,0,0,0,0,0,0};
        const int ng = (cnt + 3) >> 2;
        for (int g = 0; g < ng; g++) {
            asm volatile("cp.async.wait_group 1;" ::: "memory");
            const int base = g * 4;
            __half2 h0 = hz, h1 = hz, h2 = hz, h3 = hz;
            #pragma unroll
            for (int r = 0; r < 4; r++) {
                int row = base + r;
                float p = (row < cnt) ? ps[wid][row] : 0.0f;
                __half2 ph = __float2half2_rn(p);
                uint4 vv = vring[wid][row & 7][lane];
                const __half2* hp = reinterpret_cast<const __half2*>(&vv);
                h0 = __hfma2(ph, hp[0], h0);
                h1 = __hfma2(ph, hp[1], h1);
                h2 = __hfma2(ph, hp[2], h2);
                h3 = __hfma2(ph, hp[3], h3);
            }
            float2 f0 = __half22float2(h0), f1 = __half22float2(h1);
            float2 f2 = __half22float2(h2), f3 = __half22float2(h3);
            acc[0] += f0.x; acc[1] += f0.y; acc[2] += f1.x; acc[3] += f1.y;
            acc[4] += f2.x; acc[5] += f2.y; acc[6] += f3.x; acc[7] += f3.y;
            #pragma unroll
            for (int r = 0; r < 4; r++) {
                int row = base + 8 + r;
                int idx = (row < cnt) ? row : cm1;
                cp16(ringb + (uint32_t)(row & 7) * 512u, vh + (size_t)js[wid][idx]*HID + lane*8);
            }
            asm volatile("cp.async.commit_group;" ::: "memory");
        }

        #pragma unroll
        for (int e = 0; e < 8; e++) {
            float val = acc[e] * sinv + gcb[lane*8 + e];
            outv[e] = 1.0f / (1.0f + __expf(-val));
        }
    } else {
        #pragma unroll
        for (int e = 0; e < 8; e++)
            outv[e] = 1.0f / (1.0f + __expf(-gcb[lane*8 + e]));
    }

    if (LAST) {
        float a0 = 0.0f, a1 = 0.0f;
        #pragma unroll
        for (int e = 0; e < 8; e++) {
            int c = lane*8 + e;
            a0 = fmaf(outv[e], Wc[2*c],     a0);
            a1 = fmaf(outv[e], Wc[2*c + 1], a1);
        }
        #pragma unroll
        for (int o = 16; o; o >>= 1) {
            a0 += __shfl_xor_sync(0xffffffffu, a0, o);
            a1 += __shfl_xor_sync(0xffffffffu, a1, o);
        }
        if (lane == 0) {
            a0 += bc[0]; a1 += bc[1];
            float m = fmaxf(a0, a1);
            float e0 = __expf(a0 - m), e1 = __expf(a1 - m);
            float inv = 1.0f / (e0 + e1);
            out[node*2 + 0] = e0 * inv;
            out[node*2 + 1] = e1 * inv;
        }
    } else {
        __half2 ov[4];
        #pragma unroll
        for (int e = 0; e < 4; e++)
            ov[e] = __floats2half2_rn(outv[2*e], outv[2*e+1]);
        *reinterpret_cast<uint4*>(hout + (size_t)node*HID + lane*8) = *reinterpret_cast<uint4*>(ov);
    }
}

// ---------------- launch ----------------
extern "C" void kernel_launch(void* const* d_in, const int* in_sizes, int n_in,
                              void* d_out, int out_size) {
    const int*   x   = (const int*)  d_in[0];
    const int*   cue = (const int*)  d_in[1];
    const float* adj = (const float*)d_in[2];
    const float* emb = (const float*)d_in[3];
    const float* Wh  = (const float*)d_in[4];
    const float* bh  = (const float*)d_in[5];
    const float* Wq  = (const float*)d_in[6];
    const float* Wk  = (const float*)d_in[7];
    const float* Wv  = (const float*)d_in[8];
    const float* gcb = (const float*)d_in[9];
    const float* Wc  = (const float*)d_in[10];
    const float* bc  = (const float*)d_in[11];
    float* out = (float*)d_out;

    void *p_feats, *p_h0, *p_h1, *p_q, *p_kh, *p_vh, *p_WhT, *p_WqkvT;
    cudaGetSymbolAddress(&p_feats, g_feats);
    cudaGetSymbolAddress(&p_h0,    g_h0);
    cudaGetSymbolAddress(&p_h1,    g_h1);
    cudaGetSymbolAddress(&p_q,     g_q);
    cudaGetSymbolAddress(&p_kh,    g_kh);
    cudaGetSymbolAddress(&p_vh,    g_vh);
    cudaGetSymbolAddress(&p_WhT,   g_WhT);
    cudaGetSymbolAddress(&p_WqkvT, g_WqkvT);
    __half* feats = (__half*)p_feats;
    __half* h0    = (__half*)p_h0;
    __half* h1    = (__half*)p_h1;
    __half* qbuf  = (__half*)p_q;
    __half* khb   = (__half*)p_kh;
    __half* vhb   = (__half*)p_vh;
    __half* WhT   = (__half*)p_WhT;
    __half* WqkvT = (__half*)p_WqkvT;

    cudaFuncSetAttribute(gemm_h_kernel<0>, cudaFuncAttributeMaxDynamicSharedMemorySize, SMEM_BYTES);
    cudaFuncSetAttribute(gemm_h_kernel<1>, cudaFuncAttributeMaxDynamicSharedMemorySize, SMEM_BYTES);

    prep_kernel<<<NB_NBR + NB_FEATS + NB_W, 256>>>(adj, x, cue, emb, Wh, Wq, Wk, Wv);

    gemm_h_kernel<0><<<dim3(2, 128), 256, SMEM_BYTES>>>(feats, WhT, h0, bh, nullptr, nullptr, nullptr);

    // layer 0
    gemm_h_kernel<1><<<dim3(3, 128), 256, SMEM_BYTES>>>(h0, WqkvT, nullptr, nullptr, qbuf, khb, vhb);
    attn_kernel<0><<<MTOT/8, 256>>>(qbuf, khb, vhb, h1, gcb, nullptr, nullptr, nullptr);

    // layer 1 + fused classifier
    gemm_h_kernel<1><<<dim3(3, 128), 256, SMEM_BYTES>>>(h1, WqkvT, nullptr, nullptr, qbuf, khb, vhb);
    attn_kernel<1><<<MTOT/8, 256>>>(qbuf, khb, vhb, nullptr, gcb, Wc, bc, out);
}